// round 7
// baseline (speedup 1.0000x reference)
#include <cuda_runtime.h>
#include <cuda_fp16.h>
#include <math.h>
#include <stdint.h>

// ---------------- problem constants ----------------
#define Bb   256
#define Ss   32
#define VFd  512
#define IFd  256
#define Ff   768
#define Hh   1024
#define Ll   2
#define Kk   8
#define MB   (Ll*Bb)
#define G3F  (3*Ff)

// ---------------- standalone GEMM tiling (prologue/epilogue) ----------------
#define BM 64
#define BN 64
#define BK 64
#define ROWB   144
#define PLANE  (64*ROWB)
#define STAGE_BYTES (2*PLANE)
#define NSTAGE 4
#define SMEM_TOTAL (NSTAGE*STAGE_BYTES)  // 73728

// ---------------- cluster-kernel tiling: M32 x N128 x K64 ----------------
#define CBK 64
#define CROWB 144
#define CA_BYTES (32*CROWB)              // 4608
#define CB_BYTES (128*CROWB)             // 18432
#define CSTAGE   (CA_BYTES + CB_BYTES)   // 23040
#define CSEQ_SMEM (4*CSTAGE)             // 92160

// ---------------- persistent device scratch ----------------
__device__ __align__(16) float  g_dt  [Ss*Bb];
__device__ __align__(16) float  g_Y   [MB*Ff];
__device__ __align__(16) __half g_Yh  [MB*Ff];
__device__ __align__(16) __half g_xh  [Ss*Bb*Ff];
__device__ __align__(16) float  g_a1  [MB*Hh];
__device__ __align__(16) __half g_h1h [MB*Hh];
__device__ __align__(16) __half g_h2h [MB*Hh];
__device__ __align__(16) __half g_S   [MB*Hh];
__device__ __align__(16) __half g_x1h [Bb*Ff];
__device__ __align__(16) __half g_outh[Ss*Bb*Ff];
__device__ __align__(16) float  g_gx0 [Ss*Bb*G3F];
__device__ __align__(16) float  g_gh  [2*Bb*G3F];
__device__ __align__(16) float  g_gx1 [Bb*G3F];
__device__ __align__(16) float  g_hid [Ss*Bb*128];
__device__ __align__(16) float  g_c0  [Hh];
// fp16 weights
__device__ __align__(16) __half g_W0h [Hh*Ff];
__device__ __align__(16) __half g_W1h [Hh*Hh];
__device__ __align__(16) __half g_W2h [Ff*Hh];     // W2 as [768,1024]
__device__ __align__(16) __half g_W2Th[Hh*Ff];     // W2^T as [1024,768]
__device__ __align__(16) float  g_W20f[Hh*Hh];
__device__ __align__(16) __half g_W20h[Hh*Hh];     // W0@W2 [1024,1024]
__device__ __align__(16) __half g_Wxh [Ll*G3F*Ff];
__device__ __align__(16) __half g_Whh [Ll*G3F*Ff];
__device__ __align__(16) __half g_rW1h[128*Ff];

// ---------------- asm helpers ----------------
__device__ __forceinline__ uint32_t smem_u32(const void* p) {
    uint32_t a;
    asm("{ .reg .u64 t; cvta.to.shared.u64 t, %1; cvt.u32.u64 %0, t; }" : "=r"(a) : "l"(p));
    return a;
}
__device__ __forceinline__ void cp16(uint32_t dst, const void* src) {
    asm volatile("cp.async.cg.shared.global [%0], [%1], 16;" :: "r"(dst), "l"(src));
}
__device__ __forceinline__ void ldm_x4(uint32_t addr, uint32_t r[4]) {
    asm volatile("ldmatrix.sync.aligned.m8n8.x4.shared.b16 {%0,%1,%2,%3}, [%4];"
                 : "=r"(r[0]), "=r"(r[1]), "=r"(r[2]), "=r"(r[3]) : "r"(addr));
}
__device__ __forceinline__ void mma16816(float d[4], const uint32_t a[4],
                                         uint32_t b0, uint32_t b1) {
    asm volatile("mma.sync.aligned.m16n8k16.row.col.f32.f16.f16.f32 "
                 "{%0,%1,%2,%3}, {%4,%5,%6,%7}, {%8,%9}, {%0,%1,%2,%3};"
                 : "+f"(d[0]), "+f"(d[1]), "+f"(d[2]), "+f"(d[3])
                 : "r"(a[0]), "r"(a[1]), "r"(a[2]), "r"(a[3]), "r"(b0), "r"(b1));
}
__device__ __forceinline__ void csync() {
    __threadfence();
    asm volatile("barrier.cluster.arrive.aligned;" ::: "memory");
    asm volatile("barrier.cluster.wait.aligned;" ::: "memory");
}

// ================= cluster GEMM tile: 32x128, 256 thr (2x4 warps) =================
enum { CE_A1 = 0, CE_H2, CE_DA1, CE_YUPD, CE_GH, CE_GX1 };

template<int EPI>
__device__ __noinline__ void ctile(
    const __half* __restrict__ A, int lda, int rowmode, int rowbase, int cbase,
    const __half* __restrict__ Bw,    // weight slice base (already + n0*Kd)
    const float* __restrict__ bias,   // already + n0 (nullptr ok)
    int Kd, int n0,
    const float* __restrict__ dtv,    // g_dt + t*Bb
    int kflag, int outbase)
{
    extern __shared__ char smem[];
    const uint32_t sb0 = smem_u32(smem);
    const int tid = threadIdx.x;
    const int wid = tid >> 5, lane = tid & 31;
    const int warp_m = wid & 1, warp_n = wid >> 1;

    auto grow = [&](int i) -> int {
        return (rowmode == 0) ? (((i >> 4) << 8) + cbase + (i & 15))
                              : (rowbase + (i & 15));
    };

    auto issue = [&](int c) {
        const int k0 = c * CBK;
        const uint32_t st = sb0 + (uint32_t)(c & 3) * CSTAGE;
        {   // A: 32 rows x 8 chunks = 256
            int row = tid >> 3, ch = tid & 7;
            cp16(st + row*CROWB + ch*16, A + (size_t)grow(row)*lda + k0 + ch*8);
        }
#pragma unroll
        for (int j = 0; j < 4; j++) {  // B: 128 rows x 8 chunks = 1024
            int u = tid + j*256;
            int row = u >> 3, ch = u & 7;
            cp16(st + CA_BYTES + row*CROWB + ch*16, Bw + (size_t)row*Kd + k0 + ch*8);
        }
        asm volatile("cp.async.commit_group;");
    };

    float acc[4][4];
#pragma unroll
    for (int i = 0; i < 4; i++)
#pragma unroll
        for (int e = 0; e < 4; e++) acc[i][e] = 0.0f;

    const int nc = Kd / CBK;
    issue(0); issue(1); issue(2);

    const int arow = lane & 15, acol8 = (lane >> 4) * 8;
    const uint32_t aoff = (uint32_t)(warp_m*16 + arow)*CROWB + acol8*2;
    const int brow = ((lane >> 4) & 1)*8 + (lane & 7);
    const int bcol8 = ((lane >> 3) & 1)*8;
    const uint32_t boff = CA_BYTES + (uint32_t)(warp_n*32 + brow)*CROWB + bcol8*2;

    for (int c = 0; c < nc; c++) {
        if (c + 2 < nc)      { asm volatile("cp.async.wait_group 2;"); }
        else if (c + 1 < nc) { asm volatile("cp.async.wait_group 1;"); }
        else                 { asm volatile("cp.async.wait_group 0;"); }
        __syncthreads();
        if (c + 3 < nc) issue(c + 3);

        const uint32_t st = sb0 + (uint32_t)(c & 3) * CSTAGE;
#pragma unroll
        for (int kk = 0; kk < 4; kk++) {
            uint32_t ar[4], br0[4], br1[4];
            ldm_x4(st + aoff + kk*32, ar);
            ldm_x4(st + boff + kk*32, br0);
            ldm_x4(st + boff + 16*CROWB + kk*32, br1);
            mma16816(acc[0], ar, br0[0], br0[1]);
            mma16816(acc[1], ar, br0[2], br0[3]);
            mma16816(acc[2], ar, br1[0], br1[1]);
            mma16816(acc[3], ar, br1[2], br1[3]);
        }
        __syncthreads();
    }

    const int rb = lane >> 2, cb2 = (lane & 3)*2;
#pragma unroll
    for (int n8 = 0; n8 < 4; n8++) {
#pragma unroll
        for (int half = 0; half < 2; half++) {
            const int ml = warp_m*16 + rb + half*8;     // 0..31
            const int nl = warp_n*32 + n8*8 + cb2;      // 0..127
            float v0 = acc[n8][half*2 + 0];
            float v1 = acc[n8][half*2 + 1];
            const int gr = grow(ml);
            const int n  = n0 + nl;

            if (EPI == CE_A1) {
                v0 += __ldg(bias + nl); v1 += __ldg(bias + nl + 1);
                size_t o = (size_t)gr*Hh + n;
                g_a1[o] = v0; g_a1[o+1] = v1;
                g_h1h[o]   = __float2half_rn(tanhf(v0));
                g_h1h[o+1] = __float2half_rn(tanhf(v1));
            } else if (EPI == CE_H2) {
                v0 = tanhf(v0 + __ldg(bias + nl));
                v1 = tanhf(v1 + __ldg(bias + nl + 1));
                size_t o = (size_t)gr*Hh + n;
                g_h2h[o]   = __float2half_rn(v0);
                g_h2h[o+1] = __float2half_rn(v1);
                if (kflag) {
                    g_S[o]   = __float2half_rn(v0);
                    g_S[o+1] = __float2half_rn(v1);
                } else {
                    g_S[o]   = __float2half_rn(__half2float(g_S[o])   + v0);
                    g_S[o+1] = __float2half_rn(__half2float(g_S[o+1]) + v1);
                }
            } else if (EPI == CE_DA1) {
                const float sub = __ldg(dtv + (gr & 255)) * (1.0f / Kk);
                size_t o = (size_t)gr*Hh + n;
                float a0 = g_a1[o]   + sub*(v0 + __ldg(g_c0 + n));
                float a1v = g_a1[o+1] + sub*(v1 + __ldg(g_c0 + n + 1));
                g_a1[o] = a0; g_a1[o+1] = a1v;
                g_h1h[o]   = __float2half_rn(tanhf(a0));
                g_h1h[o+1] = __float2half_rn(tanhf(a1v));
            } else if (EPI == CE_YUPD) {
                const float sub = __ldg(dtv + (gr & 255)) * (1.0f / Kk);
                size_t o = (size_t)gr*Ff + n;
                float y0 = g_Y[o]   + sub*v0 + 8.0f*sub*__ldg(bias + nl);
                float y1 = g_Y[o+1] + sub*v1 + 8.0f*sub*__ldg(bias + nl + 1);
                g_Y[o] = y0; g_Y[o+1] = y1;
                g_Yh[o]   = __float2half_rn(y0);
                g_Yh[o+1] = __float2half_rn(y1);
            } else if (EPI == CE_GH) {
                if (ml < 16) {
                    size_t o = (size_t)(outbase + ml)*G3F + n;
                    g_gh[o]   = v0 + __ldg(bias + nl);
                    g_gh[o+1] = v1 + __ldg(bias + nl + 1);
                }
            } else if (EPI == CE_GX1) {
                if (ml < 16) {
                    size_t o = (size_t)(outbase + ml)*G3F + n;
                    g_gx1[o]   = v0 + __ldg(bias + nl);
                    g_gx1[o+1] = v1 + __ldg(bias + nl + 1);
                }
            }
        }
    }
}

// GRU combine, cluster-local (16 batch rows, 8 CTAs x 256 thr)
__device__ __forceinline__ void gru_cluster(
    const float* __restrict__ gx, const float* __restrict__ gh,
    int hbase, int cbase, int r,
    __half* __restrict__ xouth, __half* __restrict__ outh)
{
    const int gid = r*256 + threadIdx.x;
    for (int idx = gid; idx < 16*Ff; idx += 2048) {
        int bl = idx / Ff, f = idx % Ff;
        int b = cbase + bl;
        const float* gxr = gx + (size_t)b*G3F;
        const float* ghr = gh + (size_t)b*G3F;
        size_t ho = (size_t)(hbase + b)*Ff + f;
        float rr = 1.0f/(1.0f + expf(-(gxr[f]      + ghr[f]     )));
        float zz = 1.0f/(1.0f + expf(-(gxr[f+Ff]   + ghr[f+Ff]  )));
        float nn = tanhf(gxr[f+2*Ff] + rr*ghr[f+2*Ff]);
        float hn = (1.0f - zz)*nn + zz*g_Y[ho];
        g_Y[ho] = hn;
        __half hv = __float2half_rn(hn);
        g_Yh[ho] = hv;
        if (xouth) xouth[(size_t)b*Ff + f] = hv;
        if (outh)  outh[(size_t)b*Ff + f] = hv;
    }
}

// ================= the persistent cluster sequence kernel =================
__global__ void __cluster_dims__(8, 1, 1) __launch_bounds__(256, 1)
k_seq(const float* __restrict__ b0, const float* __restrict__ b1,
      const float* __restrict__ b2o, const float* __restrict__ gbx,
      const float* __restrict__ gbh)
{
    const int c = blockIdx.x >> 3;     // cluster 0..15
    const int r = blockIdx.x & 7;      // rank 0..7
    const int cbase = c * 16;
    const int n0 = r * 128;

    for (int t = 0; t < Ss; t++) {
        const float* dtv = g_dt + t*Bb;

        // P0: a1 = Yh @ W0^T + b0 ; h1 = tanh(a1)
        ctile<CE_A1>(g_Yh, Ff, 0, 0, cbase, g_W0h + (size_t)n0*Ff, b0 + n0,
                     Ff, n0, nullptr, 0, 0);
        csync();

        for (int k = 0; k < Kk; k++) {
            // phase A: h2 = tanh(h1 @ W1^T + b1); S (+)= h2
            ctile<CE_H2>(g_h1h, Hh, 0, 0, cbase, g_W1h + (size_t)n0*Hh, b1 + n0,
                         Hh, n0, nullptr, (k == 0), 0);
            csync();
            if (k < Kk - 1) {
                // phase B: a1 += sub*(h2 @ W20^T + c0); h1 = tanh(a1)
                ctile<CE_DA1>(g_h2h, Hh, 0, 0, cbase, g_W20h + (size_t)n0*Hh, nullptr,
                              Hh, n0, dtv, 0, 0);
                csync();
            }
        }

        // P3: Y += sub*(S @ W2^T) + 8*sub*b2 (N=768 -> ranks 0..5)
        if (r < 6)
            ctile<CE_YUPD>(g_S, Hh, 0, 0, cbase, g_W2h + (size_t)n0*Hh, b2o + n0,
                           Hh, n0, dtv, 0, 0);
        csync();

        // P4: gh[l] = Yh[l] @ Wh[l]^T + bh[l]  (36 tiles over 8 ranks)
        for (int tt = r; tt < 36; tt += 8) {
            int l = tt / 18, nt = tt % 18, nn0 = nt*128;
            ctile<CE_GH>(g_Yh, Ff, 1, l*256 + cbase, cbase,
                         g_Whh + (size_t)l*G3F*Ff + (size_t)nn0*Ff,
                         gbh + l*G3F + nn0, Ff, nn0, nullptr, 0, l*256 + cbase);
        }
        csync();

        // P5: GRU layer 0
        gru_cluster(g_gx0 + (size_t)t*Bb*G3F, g_gh, 0, cbase, r, g_x1h, nullptr);
        csync();

        // P6: gx1 = x1 @ Wx1^T + bx1 (18 tiles over 8 ranks)
        for (int tt = r; tt < 18; tt += 8) {
            int nn0 = tt*128;
            ctile<CE_GX1>(g_x1h, Ff, 1, cbase, cbase,
                          g_Wxh + (size_t)G3F*Ff + (size_t)nn0*Ff,
                          gbx + G3F + nn0, Ff, nn0, nullptr, 0, cbase);
        }
        csync();

        // P7: GRU layer 1 -> out[t]
        gru_cluster(g_gx1, g_gh + (size_t)256*G3F, 256, cbase, r,
                    nullptr, g_outh + (size_t)t*Bb*Ff);
        csync();
    }
}

// ================= standalone 64x64 GEMM (prologue / epilogue) =================
enum { EPI_STORE = 0, EPI_LRELU = 3 };

template<int EPI>
__global__ void __launch_bounds__(256)
k_mgemm(const __half* __restrict__ A, int lda,
        const __half* __restrict__ Bm, int ldb,
        const float* __restrict__ bias,
        float* __restrict__ Cf, int ldc, int Kd)
{
    extern __shared__ char smem[];
    __shared__ float sbias[BN];
    const uint32_t smem_base = smem_u32(smem);
    const int tid = threadIdx.x;
    const int wid = tid >> 5, lane = tid & 31;
    const int m0 = blockIdx.y << 6, n0 = blockIdx.x << 6;
    const int warp_m = wid & 1, warp_n = wid >> 1;

    if (tid < BN) sbias[tid] = bias ? bias[n0 + tid] : 0.0f;

    const int l_row = tid >> 2;
    const int l_c16a = tid & 3;

    auto issue_stage = [&](int c) {
        const int k0 = c * BK;
        const uint32_t sb = smem_base + (uint32_t)(c % NSTAGE) * STAGE_BYTES;
#pragma unroll
        for (int i = 0; i < 2; i++) {
            const int c16 = l_c16a + i * 4;
            const uint32_t dst = sb + (uint32_t)l_row * ROWB + c16 * 16;
            cp16(dst,         A  + (size_t)(m0 + l_row) * lda + k0 + c16 * 8);
            cp16(dst + PLANE, Bm + (size_t)(n0 + l_row) * ldb + k0 + c16 * 8);
        }
        asm volatile("cp.async.commit_group;");
    };

    float acc[2][2][4];
#pragma unroll
    for (int mi = 0; mi < 2; mi++)
#pragma unroll
        for (int nj = 0; nj < 2; nj++)
#pragma unroll
            for (int e = 0; e < 4; e++) acc[mi][nj][e] = 0.0f;

    const int nc = Kd / BK;
    issue_stage(0);
    issue_stage(1);
    if (nc > 2) issue_stage(2);

    const int arow = lane & 15, acol8 = (lane >> 4) * 8;
    const int brow = ((lane >> 4) & 1) * 8 + (lane & 7);
    const int bcol8 = ((lane >> 3) & 1) * 8;
    const uint32_t aoff = (uint32_t)(warp_m*32 + arow) * ROWB + acol8 * 2;
    const uint32_t boff = PLANE + (uint32_t)(warp_n*16 + brow) * ROWB + bcol8 * 2;

    for (int c = 0; c < nc; c++) {
        if (c + 2 < nc)      { asm volatile("cp.async.wait_group 2;"); }
        else if (c + 1 < nc) { asm volatile("cp.async.wait_group 1;"); }
        else                 { asm volatile("cp.async.wait_group 0;"); }
        __syncthreads();
        if (c + 3 < nc) issue_stage(c + 3);

        const uint32_t sb = smem_base + (uint32_t)(c % NSTAGE) * STAGE_BYTES;
#pragma unroll
        for (int kk = 0; kk < 4; kk++) {
            uint32_t ah[2][4], bh[4];
#pragma unroll
            for (int mi = 0; mi < 2; mi++)
                ldm_x4(sb + aoff + mi*16*ROWB + kk*32, ah[mi]);
            ldm_x4(sb + boff + kk*32, bh);
#pragma unroll
            for (int mi = 0; mi < 2; mi++)
#pragma unroll
                for (int nj = 0; nj < 2; nj++)
                    mma16816(acc[mi][nj], ah[mi], bh[nj*2], bh[nj*2+1]);
        }
        __syncthreads();
    }

    const int rbase = lane >> 2;
    const int cbase2 = (lane & 3) * 2;
#pragma unroll
    for (int mi = 0; mi < 2; mi++) {
#pragma unroll
        for (int nj = 0; nj < 2; nj++) {
#pragma unroll
            for (int half = 0; half < 2; half++) {
                const int m = m0 + warp_m*32 + mi*16 + rbase + half*8;
                const int nl = warp_n*16 + nj*8 + cbase2;
                float v0 = acc[mi][nj][half*2 + 0] + sbias[nl];
                float v1 = acc[mi][nj][half*2 + 1] + sbias[nl + 1];
                if (EPI == EPI_LRELU) {
                    v0 = (v0 > 0.f) ? v0 : 0.1f*v0;
                    v1 = (v1 > 0.f) ? v1 : 0.1f*v1;
                }
                *(float2*)(Cf + (size_t)m*ldc + n0 + nl) = make_float2(v0, v1);
            }
        }
    }
}

// ---------------- prep kernels ----------------
__global__ void k_cvt(const float* __restrict__ src, __half* __restrict__ dst, int n) {
    int stride = gridDim.x * blockDim.x;
    for (int i = blockIdx.x*blockDim.x + threadIdx.x; i < n; i += stride)
        dst[i] = __float2half_rn(src[i]);
}

// dst[C][R] = src[R][C] as fp16
__global__ void k_transpose(const float* __restrict__ src, __half* __restrict__ dst,
                            int R, int C) {
    int stride = gridDim.x * blockDim.x;
    for (int i = blockIdx.x*blockDim.x + threadIdx.x; i < R*C; i += stride) {
        int cc = i / R, rr = i % R;
        dst[(size_t)cc*R + rr] = __float2half_rn(src[(size_t)rr*C + cc]);
    }
}

__global__ void k_c0(const float* __restrict__ W0, const float* __restrict__ b2) {
    int i = blockIdx.x*blockDim.x + threadIdx.x;
    if (i >= Hh) return;
    const float* row = W0 + (size_t)i*Ff;
    float acc = 0.0f;
#pragma unroll 8
    for (int f = 0; f < Ff; f++) acc += row[f] * b2[f];
    g_c0[i] = acc;
}

__global__ void k_prep_x(const float* __restrict__ fv, const float* __restrict__ fi) {
    int stride = gridDim.x * blockDim.x;
    int total = Ss*Bb*Ff;
    for (int idx = blockIdx.x*blockDim.x + threadIdx.x; idx < total; idx += stride) {
        int f = idx % Ff;
        int sb = idx / Ff;
        int b = sb % Bb, s = sb / Bb;
        float v = (f < VFd) ? fv[(b*Ss + s)*VFd + f] : fi[(b*Ss + s)*IFd + (f - VFd)];
        g_xh[idx] = __float2half_rn(v);
    }
}

__global__ void k_prep_misc(const float* __restrict__ ts) {
    int stride = gridDim.x * blockDim.x;
    int gtid = blockIdx.x*blockDim.x + threadIdx.x;
    for (int i = gtid; i < MB*Ff; i += stride) {
        g_Y[i] = 0.0f; g_Yh[i] = __float2half(0.0f);
    }
    for (int i = gtid; i < Ss*Bb; i += stride) {
        int s = i / Bb, b = i % Bb;
        g_dt[i] = (s < Ss-1) ? (ts[b*Ss + s + 1] - ts[b*Ss + s]) : 0.0f;
    }
}

// ---------------- regressor second layer (N=6) ----------------
__global__ void k_pose(const float* __restrict__ W2, const float* __restrict__ b2,
                       float* __restrict__ outp)
{
    int idx = blockIdx.x*blockDim.x + threadIdx.x;
    if (idx >= Ss*Bb*6) return;
    int n = idx % 6;
    int m = idx / 6;
    int b = m % Bb, s = m / Bb;
    const float* hrow = g_hid + (size_t)m * 128;
    const float* wrow = W2 + n * 128;
    float acc = b2[n];
#pragma unroll 8
    for (int k = 0; k < 128; k++) acc += hrow[k] * wrow[k];
    outp[(b*Ss + s)*6 + n] = acc;
}

__global__ void k_copyY(float* __restrict__ outp) {
    int stride = gridDim.x * blockDim.x;
    for (int i = blockIdx.x*blockDim.x + threadIdx.x; i < MB*Ff; i += stride)
        outp[i] = g_Y[i];
}

// ---------------- launch ----------------
extern "C" void kernel_launch(void* const* d_in, const int* in_sizes, int n_in,
                              void* d_out, int out_size)
{
    const float* fv  = (const float*)d_in[0];
    const float* fi  = (const float*)d_in[1];
    const float* ts  = (const float*)d_in[2];
    const float* W0  = (const float*)d_in[3];
    const float* b0  = (const float*)d_in[4];
    const float* W1  = (const float*)d_in[5];
    const float* b1  = (const float*)d_in[6];
    const float* W2o = (const float*)d_in[7];
    const float* b2o = (const float*)d_in[8];
    const float* gWx = (const float*)d_in[9];
    const float* gWh = (const float*)d_in[10];
    const float* gbx = (const float*)d_in[11];
    const float* gbh = (const float*)d_in[12];
    const float* rW1 = (const float*)d_in[13];
    const float* rb1 = (const float*)d_in[14];
    const float* rW2 = (const float*)d_in[15];
    const float* rb2 = (const float*)d_in[16];

    cudaFuncSetAttribute(k_mgemm<EPI_STORE>, cudaFuncAttributeMaxDynamicSharedMemorySize, SMEM_TOTAL);
    cudaFuncSetAttribute(k_mgemm<EPI_LRELU>, cudaFuncAttributeMaxDynamicSharedMemorySize, SMEM_TOTAL);
    cudaFuncSetAttribute(k_seq, cudaFuncAttributeMaxDynamicSharedMemorySize, CSEQ_SMEM);

#define SYM(p, s) float* p; cudaGetSymbolAddress((void**)&p, s)
#define SYMH(p, s) __half* p; cudaGetSymbolAddress((void**)&p, s)
    SYM(pgx0, g_gx0); SYM(phid, g_hid); SYM(pW20f, g_W20f);
    SYMH(pxh, g_xh); SYMH(pouth, g_outh);
    SYMH(pW0h, g_W0h); SYMH(pW1h, g_W1h); SYMH(pW2h, g_W2h);
    SYMH(pW2Th, g_W2Th); SYMH(pW20h, g_W20h);
    SYMH(pWxh, g_Wxh); SYMH(pWhh, g_Whh); SYMH(prW1, g_rW1h);
#undef SYM
#undef SYMH

    // weight prep (deterministic every call)
    k_cvt<<<256, 256>>>(W0,  pW0h, Hh*Ff);
    k_cvt<<<256, 256>>>(W1,  pW1h, Hh*Hh);
    k_cvt<<<256, 256>>>(W2o, pW2h, Ff*Hh);
    k_cvt<<<256, 256>>>(gWx, pWxh, Ll*G3F*Ff);
    k_cvt<<<256, 256>>>(gWh, pWhh, Ll*G3F*Ff);
    k_cvt<<<64,  256>>>(rW1, prW1, 128*Ff);
    k_transpose<<<256, 256>>>(W2o, pW2Th, Ff, Hh);       // W2T [1024,768]
    k_c0<<<(Hh + 255)/256, 256>>>(W0, b2o);
    // W20 = W0 @ W2  (A=W0h [1024,768], B=W2T [1024,768])
    k_mgemm<EPI_STORE><<<dim3(Hh/BN, Hh/BM), 256, SMEM_TOTAL>>>(
        pW0h, Ff, pW2Th, Ff, nullptr, pW20f, Hh, Ff);
    k_cvt<<<256, 256>>>(pW20f, pW20h, Hh*Hh);

    k_prep_x<<<512, 256>>>(fv, fi);
    k_prep_misc<<<512, 256>>>(ts);

    // hoisted layer-0 GRU input projection: gx0[S*B,3F] = x @ Wx0^T + bx0
    k_mgemm<EPI_STORE><<<dim3(G3F/BN, (Ss*Bb)/BM), 256, SMEM_TOTAL>>>(
        pxh, Ff, pWxh, Ff, gbx, pgx0, G3F, Ff);

    // the whole recurrence: 16 clusters x 8 CTAs, cluster-local syncs only
    k_seq<<<128, 256, CSEQ_SMEM>>>(b0, b1, b2o, gbx, gbh);

    // regressor
    k_mgemm<EPI_LRELU><<<dim3(128/BN, (Ss*Bb)/BM), 256, SMEM_TOTAL>>>(
        pouth, Ff, prW1, Ff, rb1, phid, 128, Ff);
    k_pose<<<(Ss*Bb*6 + 127)/128, 128>>>(rW2, rb2, (float*)d_out);

    if (out_size >= Ss*Bb*6 + MB*Ff)
        k_copyY<<<768, 256>>>((float*)d_out + Ss*Bb*6);
}

// round 8
// speedup vs baseline: 1.6660x; 1.6660x over previous
#include <cuda_runtime.h>
#include <cuda_fp16.h>
#include <math.h>
#include <stdint.h>

// ---------------- problem constants ----------------
#define Bb   256
#define Ss   32
#define VFd  512
#define IFd  256
#define Ff   768
#define Hh   1024
#define Ll   2
#define Kk   8
#define MB   (Ll*Bb)
#define G3F  (3*Ff)

// ---------------- GEMM tiling ----------------
#define BM 64
#define BN 64
#define BK 64
#define ROWB   144
#define PLANE  (64*ROWB)
#define STAGE_BYTES (2*PLANE)
#define NSTAGE 4
#define SMEM_TOTAL (NSTAGE*STAGE_BYTES)  // 73728

// ---------------- persistent device scratch ----------------
__device__ __align__(16) float  g_dt  [Ss*Bb];
__device__ __align__(16) float  g_Y   [MB*Ff];
__device__ __align__(16) __half g_Yh  [MB*Ff];
__device__ __align__(16) __half g_xh  [Ss*Bb*Ff];
__device__ __align__(16) float  g_a1  [MB*Hh];
__device__ __align__(16) __half g_h1h [MB*Hh];
__device__ __align__(16) __half g_h2h [MB*Hh];
__device__ __align__(16) float  g_Sf  [MB*Hh];
__device__ __align__(16) __half g_Sh  [MB*Hh];
__device__ __align__(16) __half g_x1h [Bb*Ff];
__device__ __align__(16) __half g_outh[Ss*Bb*Ff];
__device__ __align__(16) float  g_gx0 [Ss*Bb*G3F];
__device__ __align__(16) float  g_gh  [2*Bb*G3F];
__device__ __align__(16) float  g_gx1 [Bb*G3F];
__device__ __align__(16) float  g_hid [Ss*Bb*128];
__device__ __align__(16) float  g_c0  [Hh];
// fp16 weights
__device__ __align__(16) __half g_W0h [Hh*Ff];
__device__ __align__(16) __half g_W1h [Hh*Hh];
__device__ __align__(16) __half g_W2h [Ff*Hh];     // W2 [768,1024] row-major (native)
__device__ __align__(16) __half g_W2Th[Hh*Ff];     // W2^T [1024,768]
__device__ __align__(16) float  g_W20f[Hh*Hh];
__device__ __align__(16) __half g_W20h[Hh*Hh];     // W0@W2 [1024,1024]
__device__ __align__(16) __half g_Wxh [Ll*G3F*Ff];
__device__ __align__(16) __half g_Whh [Ll*G3F*Ff];
__device__ __align__(16) __half g_rW1h[128*Ff];

// ---------------- asm helpers ----------------
__device__ __forceinline__ uint32_t smem_u32(const void* p) {
    uint32_t a;
    asm("{ .reg .u64 t; cvta.to.shared.u64 t, %1; cvt.u32.u64 %0, t; }" : "=r"(a) : "l"(p));
    return a;
}
__device__ __forceinline__ void cp16(uint32_t dst, const void* src) {
    asm volatile("cp.async.cg.shared.global [%0], [%1], 16;" :: "r"(dst), "l"(src));
}
__device__ __forceinline__ void ldm_x4(uint32_t addr, uint32_t r[4]) {
    asm volatile("ldmatrix.sync.aligned.m8n8.x4.shared.b16 {%0,%1,%2,%3}, [%4];"
                 : "=r"(r[0]), "=r"(r[1]), "=r"(r[2]), "=r"(r[3]) : "r"(addr));
}
__device__ __forceinline__ void mma16816(float d[4], const uint32_t a[4],
                                         uint32_t b0, uint32_t b1) {
    asm volatile("mma.sync.aligned.m16n8k16.row.col.f32.f16.f16.f32 "
                 "{%0,%1,%2,%3}, {%4,%5,%6,%7}, {%8,%9}, {%0,%1,%2,%3};"
                 : "+f"(d[0]), "+f"(d[1]), "+f"(d[2]), "+f"(d[3])
                 : "r"(a[0]), "r"(a[1]), "r"(a[2]), "r"(a[3]), "r"(b0), "r"(b1));
}

// ---------------- core GEMM tile: 64x64, 256 threads ----------------
enum { EPI_STORE = 0, EPI_LRELU, EPI_A1, EPI_H2, EPI_DA1, EPI_YUPD };

template<int EPI, int KMODE>
__device__ __forceinline__ void gemm_core(
    const __half* __restrict__ A, int lda,
    const __half* __restrict__ Bm, int ldb,
    const float* __restrict__ bias,
    int m0, int n0, int Kd,
    float* __restrict__ Cf, int ldc,
    const float* __restrict__ dtv)
{
    extern __shared__ char smem[];
    __shared__ float sbias[BN];
    const uint32_t smem_base = smem_u32(smem);
    const int tid = threadIdx.x;
    const int wid = tid >> 5, lane = tid & 31;
    const int warp_m = wid & 1, warp_n = wid >> 1;

    if (tid < BN) {
        float b = bias ? bias[n0 + tid] : 0.0f;
        sbias[tid] = (EPI == EPI_YUPD) ? b * (float)Kk : b;
    }

    const int l_row = tid >> 2;
    const int l_c16a = tid & 3;

    auto issue_stage = [&](int c) {
        const int k0 = c * BK;
        const uint32_t sb = smem_base + (uint32_t)(c % NSTAGE) * STAGE_BYTES;
#pragma unroll
        for (int i = 0; i < 2; i++) {
            const int c16 = l_c16a + i * 4;
            const uint32_t dst = sb + (uint32_t)l_row * ROWB + c16 * 16;
            cp16(dst,         A  + (size_t)(m0 + l_row) * lda + k0 + c16 * 8);
            cp16(dst + PLANE, Bm + (size_t)(n0 + l_row) * ldb + k0 + c16 * 8);
        }
        asm volatile("cp.async.commit_group;");
    };

    float acc[2][2][4];
#pragma unroll
    for (int mi = 0; mi < 2; mi++)
#pragma unroll
        for (int nj = 0; nj < 2; nj++)
#pragma unroll
            for (int e = 0; e < 4; e++) acc[mi][nj][e] = 0.0f;

    const int nc = Kd / BK;
    issue_stage(0);
    issue_stage(1);
    if (nc > 2) issue_stage(2);

    const int arow = lane & 15, acol8 = (lane >> 4) * 8;
    const int brow = ((lane >> 4) & 1) * 8 + (lane & 7);
    const int bcol8 = ((lane >> 3) & 1) * 8;
    const uint32_t aoff = (uint32_t)(warp_m*32 + arow) * ROWB + acol8 * 2;
    const uint32_t boff = PLANE + (uint32_t)(warp_n*16 + brow) * ROWB + bcol8 * 2;

    for (int c = 0; c < nc; c++) {
        if (c + 2 < nc)      { asm volatile("cp.async.wait_group 2;"); }
        else if (c + 1 < nc) { asm volatile("cp.async.wait_group 1;"); }
        else                 { asm volatile("cp.async.wait_group 0;"); }
        __syncthreads();
        if (c + 3 < nc) issue_stage(c + 3);

        const uint32_t sb = smem_base + (uint32_t)(c % NSTAGE) * STAGE_BYTES;
#pragma unroll
        for (int kk = 0; kk < 4; kk++) {
            uint32_t ah[2][4], bh[4];
#pragma unroll
            for (int mi = 0; mi < 2; mi++)
                ldm_x4(sb + aoff + mi*16*ROWB + kk*32, ah[mi]);
            ldm_x4(sb + boff + kk*32, bh);
#pragma unroll
            for (int mi = 0; mi < 2; mi++)
#pragma unroll
                for (int nj = 0; nj < 2; nj++)
                    mma16816(acc[mi][nj], ah[mi], bh[nj*2], bh[nj*2+1]);
        }
        __syncthreads();
    }

    const int rbase = lane >> 2;
    const int cb2 = (lane & 3) * 2;
#pragma unroll
    for (int mi = 0; mi < 2; mi++) {
#pragma unroll
        for (int nj = 0; nj < 2; nj++) {
#pragma unroll
            for (int half = 0; half < 2; half++) {
                const int m  = m0 + warp_m*32 + mi*16 + rbase + half*8;
                const int nl = warp_n*16 + nj*8 + cb2;
                float v0 = acc[mi][nj][half*2 + 0] + sbias[nl];
                float v1 = acc[mi][nj][half*2 + 1] + sbias[nl + 1];
                const size_t o = (size_t)m * ldc + n0 + nl;
                if (EPI == EPI_A1) {
                    g_a1[o] = v0; g_a1[o+1] = v1;
                    *(__half2*)(g_h1h + o) = __floats2half2_rn(tanhf(v0), tanhf(v1));
                } else if (EPI == EPI_H2) {
                    v0 = tanhf(v0); v1 = tanhf(v1);
                    *(__half2*)(g_h2h + o) = __floats2half2_rn(v0, v1);
                    float s0, s1;
                    if (KMODE == 0) { s0 = v0; s1 = v1; }
                    else { s0 = g_Sf[o] + v0; s1 = g_Sf[o+1] + v1; }
                    g_Sf[o] = s0; g_Sf[o+1] = s1;
                    if (KMODE == 2)
                        *(__half2*)(g_Sh + o) = __floats2half2_rn(s0, s1);
                } else if (EPI == EPI_DA1) {
                    // sbias carried c0; v = (h2@W20^T + c0)
                    const float sub = __ldg(dtv + (m & (Bb - 1))) * (1.0f / Kk);
                    float a0 = g_a1[o]   + sub * v0;
                    float a1v = g_a1[o+1] + sub * v1;
                    g_a1[o] = a0; g_a1[o+1] = a1v;
                    *(__half2*)(g_h1h + o) = __floats2half2_rn(tanhf(a0), tanhf(a1v));
                } else if (EPI == EPI_YUPD) {
                    // sbias carried K*b2; Y += sub*(S@W2^T + K*b2)
                    const float sub = __ldg(dtv + (m & (Bb - 1))) * (1.0f / Kk);
                    float y0 = g_Y[o]   + sub * v0;
                    float y1 = g_Y[o+1] + sub * v1;
                    g_Y[o] = y0; g_Y[o+1] = y1;
                    *(__half2*)(g_Yh + o) = __floats2half2_rn(y0, y1);
                } else if (EPI == EPI_LRELU) {
                    v0 = (v0 > 0.f) ? v0 : 0.1f*v0;
                    v1 = (v1 > 0.f) ? v1 : 0.1f*v1;
                    *(float2*)(Cf + o) = make_float2(v0, v1);
                } else {
                    *(float2*)(Cf + o) = make_float2(v0, v1);
                }
            }
        }
    }
}

// ---------------- kernels on top of the core ----------------
template<int EPI, int KMODE = 0>
__global__ void __launch_bounds__(256)
k_mgemm(const __half* __restrict__ A, int lda,
        const __half* __restrict__ Bm, int ldb,
        const float* __restrict__ bias,
        float* __restrict__ Cf, int ldc, int Kd,
        const float* __restrict__ dtv)
{
    gemm_core<EPI, KMODE>(A, lda, Bm, ldb, bias, blockIdx.y*64, blockIdx.x*64,
                          Kd, Cf, ldc, dtv);
}

// batched GRU hidden projections (layer = blockIdx.z)
__global__ void __launch_bounds__(256)
k_gh(const float* __restrict__ gbh)
{
    const int z = blockIdx.z;
    gemm_core<EPI_STORE, 0>(g_Yh + (size_t)z*Bb*Ff, Ff,
                            g_Whh + (size_t)z*G3F*Ff, Ff,
                            gbh + z*G3F,
                            blockIdx.y*64, blockIdx.x*64, Ff,
                            g_gh + (size_t)z*Bb*G3F, G3F, nullptr);
}

// ---------------- prep / small kernels ----------------
__global__ void k_a1init(const float* __restrict__ b0) {
    int stride = gridDim.x * blockDim.x;
    for (int i = blockIdx.x*blockDim.x + threadIdx.x; i < MB*Hh; i += stride) {
        float v = b0[i & (Hh - 1)];
        g_a1[i] = v;
        g_h1h[i] = __float2half_rn(tanhf(v));
    }
}

__global__ void k_cvt_all(const float* __restrict__ W0, const float* __restrict__ W1,
                          const float* __restrict__ W2o, const float* __restrict__ gWx,
                          const float* __restrict__ gWh, const float* __restrict__ rW1)
{
    const int n0 = Hh*Ff, n1 = n0 + Hh*Hh, n2 = n1 + Ff*Hh;
    const int n3 = n2 + Ll*G3F*Ff, n4 = n3 + Ll*G3F*Ff, n5 = n4 + 128*Ff;
    int stride = gridDim.x * blockDim.x;
    for (int i = blockIdx.x*blockDim.x + threadIdx.x; i < n5; i += stride) {
        float v; __half* d;
        if      (i < n0) { v = W0[i];        d = g_W0h  + i; }
        else if (i < n1) { v = W1[i - n0];   d = g_W1h  + (i - n0); }
        else if (i < n2) { v = W2o[i - n1];  d = g_W2h  + (i - n1); }
        else if (i < n3) { v = gWx[i - n2];  d = g_Wxh  + (i - n2); }
        else if (i < n4) { v = gWh[i - n3];  d = g_Whh  + (i - n3); }
        else             { v = rW1[i - n4];  d = g_rW1h + (i - n4); }
        *d = __float2half_rn(v);
    }
}

__global__ void k_cvt(const float* __restrict__ src, __half* __restrict__ dst, int n) {
    int stride = gridDim.x * blockDim.x;
    for (int i = blockIdx.x*blockDim.x + threadIdx.x; i < n; i += stride)
        dst[i] = __float2half_rn(src[i]);
}

__global__ void k_transpose(const float* __restrict__ src, __half* __restrict__ dst,
                            int R, int C) {
    int stride = gridDim.x * blockDim.x;
    for (int i = blockIdx.x*blockDim.x + threadIdx.x; i < R*C; i += stride) {
        int cc = i / R, rr = i % R;
        dst[(size_t)cc*R + rr] = __float2half_rn(src[(size_t)rr*C + cc]);
    }
}

__global__ void k_c0(const float* __restrict__ W0, const float* __restrict__ b2) {
    int i = blockIdx.x*blockDim.x + threadIdx.x;
    if (i >= Hh) return;
    const float* row = W0 + (size_t)i*Ff;
    float acc = 0.0f;
#pragma unroll 8
    for (int f = 0; f < Ff; f++) acc += row[f] * b2[f];
    g_c0[i] = acc;
}

__global__ void k_prep_x(const float* __restrict__ fv, const float* __restrict__ fi) {
    int stride = gridDim.x * blockDim.x;
    int total = Ss*Bb*Ff;
    for (int idx = blockIdx.x*blockDim.x + threadIdx.x; idx < total; idx += stride) {
        int f = idx % Ff;
        int sb = idx / Ff;
        int b = sb % Bb, s = sb / Bb;
        float v = (f < VFd) ? fv[(b*Ss + s)*VFd + f] : fi[(b*Ss + s)*IFd + (f - VFd)];
        g_xh[idx] = __float2half_rn(v);
    }
}

__global__ void k_prep_misc(const float* __restrict__ ts) {
    int stride = gridDim.x * blockDim.x;
    int gtid = blockIdx.x*blockDim.x + threadIdx.x;
    for (int i = gtid; i < MB*Ff; i += stride) {
        g_Y[i] = 0.0f; g_Yh[i] = __float2half(0.0f);
    }
    for (int i = gtid; i < Ss*Bb; i += stride) {
        int s = i / Bb, b = i % Bb;
        g_dt[i] = (s < Ss-1) ? (ts[b*Ss + s + 1] - ts[b*Ss + s]) : 0.0f;
    }
}

// ---------------- GRU elementwise combine ----------------
__global__ void k_gru(const float* __restrict__ gx, const float* __restrict__ gh,
                      float* __restrict__ h, __half* __restrict__ hh,
                      __half* __restrict__ xh)
{
    int idx = blockIdx.x*blockDim.x + threadIdx.x;
    if (idx >= Bb*Ff) return;
    int b = idx / Ff, f = idx % Ff;
    int o = b*G3F + f;
    float r  = 1.0f / (1.0f + expf(-(gx[o]        + gh[o]       )));
    float z  = 1.0f / (1.0f + expf(-(gx[o + Ff]   + gh[o + Ff]  )));
    float n  = tanhf(gx[o + 2*Ff] + r * gh[o + 2*Ff]);
    float hn = (1.0f - z) * n + z * h[idx];
    h[idx] = hn;
    __half hv = __float2half_rn(hn);
    hh[idx] = hv;
    xh[idx] = hv;
}

// ---------------- regressor second layer (N=6) ----------------
__global__ void k_pose(const float* __restrict__ W2, const float* __restrict__ b2,
                       float* __restrict__ outp)
{
    int idx = blockIdx.x*blockDim.x + threadIdx.x;
    if (idx >= Ss*Bb*6) return;
    int n = idx % 6;
    int m = idx / 6;
    int b = m % Bb, s = m / Bb;
    const float* hrow = g_hid + (size_t)m * 128;
    const float* wrow = W2 + n * 128;
    float acc = b2[n];
#pragma unroll 8
    for (int k = 0; k < 128; k++) acc += hrow[k] * wrow[k];
    outp[(b*Ss + s)*6 + n] = acc;
}

__global__ void k_copyY(float* __restrict__ outp) {
    int stride = gridDim.x * blockDim.x;
    for (int i = blockIdx.x*blockDim.x + threadIdx.x; i < MB*Ff; i += stride)
        outp[i] = g_Y[i];
}

// ---------------- launch ----------------
extern "C" void kernel_launch(void* const* d_in, const int* in_sizes, int n_in,
                              void* d_out, int out_size)
{
    const float* fv  = (const float*)d_in[0];
    const float* fi  = (const float*)d_in[1];
    const float* ts  = (const float*)d_in[2];
    const float* W0  = (const float*)d_in[3];
    const float* b0  = (const float*)d_in[4];
    const float* W1  = (const float*)d_in[5];
    const float* b1  = (const float*)d_in[6];
    const float* W2o = (const float*)d_in[7];
    const float* b2o = (const float*)d_in[8];
    const float* gWx = (const float*)d_in[9];
    const float* gWh = (const float*)d_in[10];
    const float* gbx = (const float*)d_in[11];
    const float* gbh = (const float*)d_in[12];
    const float* rW1 = (const float*)d_in[13];
    const float* rb1 = (const float*)d_in[14];
    const float* rW2 = (const float*)d_in[15];
    const float* rb2 = (const float*)d_in[16];

#define SETSMEM(K) cudaFuncSetAttribute(K, cudaFuncAttributeMaxDynamicSharedMemorySize, SMEM_TOTAL)
    SETSMEM((k_mgemm<EPI_STORE, 0>)); SETSMEM((k_mgemm<EPI_LRELU, 0>));
    SETSMEM((k_mgemm<EPI_A1, 0>));    SETSMEM((k_mgemm<EPI_DA1, 0>));
    SETSMEM((k_mgemm<EPI_YUPD, 0>));
    SETSMEM((k_mgemm<EPI_H2, 0>)); SETSMEM((k_mgemm<EPI_H2, 1>)); SETSMEM((k_mgemm<EPI_H2, 2>));
    SETSMEM(k_gh);
#undef SETSMEM

#define SYM(p, s) float* p; cudaGetSymbolAddress((void**)&p, s)
#define SYMH(p, s) __half* p; cudaGetSymbolAddress((void**)&p, s)
    SYM(pdt, g_dt); SYM(pgx0, g_gx0); SYM(pgx1, g_gx1); SYM(pgh, g_gh);
    SYM(phid, g_hid); SYM(pW20f, g_W20f); SYM(pc0, g_c0); SYM(pY, g_Y);
    SYMH(pxh, g_xh); SYMH(pouth, g_outh); SYMH(pYh, g_Yh);
    SYMH(ph1h, g_h1h); SYMH(ph2h, g_h2h); SYMH(pSh, g_Sh); SYMH(px1h, g_x1h);
    SYMH(pW0h, g_W0h); SYMH(pW1h, g_W1h); SYMH(pW2h, g_W2h);
    SYMH(pW2Th, g_W2Th); SYMH(pW20h, g_W20h);
    SYMH(pWxh, g_Wxh); SYMH(pWhh, g_Whh); SYMH(prW1, g_rW1h);
#undef SYM
#undef SYMH

    // ---- weight prep ----
    k_cvt_all<<<1024, 256>>>(W0, W1, W2o, gWx, gWh, rW1);
    k_transpose<<<512, 256>>>(W2o, pW2Th, Ff, Hh);
    k_c0<<<(Hh + 255)/256, 256>>>(W0, b2o);
    // W20 = W0 @ W2 (fp16 inputs, fp32 out, then halve)
    k_mgemm<EPI_STORE><<<dim3(Hh/BN, Hh/BM), 256, SMEM_TOTAL>>>(
        pW0h, Ff, pW2Th, Ff, nullptr, pW20f, Hh, Ff, nullptr);
    k_cvt<<<512, 256>>>(pW20f, pW20h, Hh*Hh);

    k_prep_x<<<512, 256>>>(fv, fi);
    k_prep_misc<<<512, 256>>>(ts);

    // hoisted layer-0 GRU input projection
    k_mgemm<EPI_STORE><<<dim3(G3F/BN, (Ss*Bb)/BM), 256, SMEM_TOTAL>>>(
        pxh, Ff, pWxh, Ff, gbx, pgx0, G3F, Ff, nullptr);

    const int gruBlocks = (Bb*Ff + 255) / 256;
    const dim3 gridH(Hh/BN, MB/BM);     // 16 x 8
    const dim3 gridYU(Ff/BN, MB/BM);    // 12 x 8

    for (int t = 0; t < Ss; t++) {
        const float* dtv = pdt + t*Bb;
        if (t < Ss - 1) {   // t = Ss-1 has dt == 0 -> ODE is identity, skip
            // a1 = Yh @ W0^T + b0 ; h1 = tanh(a1)
            if (t == 0)
                k_a1init<<<512, 256>>>(b0);
            else
                k_mgemm<EPI_A1><<<gridH, 256, SMEM_TOTAL>>>(
                    pYh, Ff, pW0h, Ff, b0, nullptr, Hh, Ff, nullptr);
            for (int k = 0; k < Kk; k++) {
                // h2 = tanh(h1 @ W1^T + b1); S (+)= h2
                if (k == 0)
                    k_mgemm<EPI_H2, 0><<<gridH, 256, SMEM_TOTAL>>>(
                        ph1h, Hh, pW1h, Hh, b1, nullptr, Hh, Hh, nullptr);
                else if (k < Kk - 1)
                    k_mgemm<EPI_H2, 1><<<gridH, 256, SMEM_TOTAL>>>(
                        ph1h, Hh, pW1h, Hh, b1, nullptr, Hh, Hh, nullptr);
                else
                    k_mgemm<EPI_H2, 2><<<gridH, 256, SMEM_TOTAL>>>(
                        ph1h, Hh, pW1h, Hh, b1, nullptr, Hh, Hh, nullptr);
                // a1 += sub*(h2 @ W20^T + c0); h1 = tanh(a1)
                if (k < Kk - 1)
                    k_mgemm<EPI_DA1><<<gridH, 256, SMEM_TOTAL>>>(
                        ph2h, Hh, pW20h, Hh, pc0, nullptr, Hh, Hh, dtv);
            }
            // Y += sub*(S @ W2^T) + dt*b2
            k_mgemm<EPI_YUPD><<<gridYU, 256, SMEM_TOTAL>>>(
                pSh, Hh, pW2h, Hh, b2o, nullptr, Ff, Hh, dtv);
        }
        // GRU hidden projections (both layers)
        k_gh<<<dim3(G3F/BN, Bb/BM, 2), 256, SMEM_TOTAL>>>(gbh);
        // GRU layer 0
        k_gru<<<gruBlocks, 256>>>(pgx0 + (size_t)t*Bb*G3F, pgh, pY, pYh, px1h);
        // GRU layer 1 input projection + combine
        k_mgemm<EPI_STORE><<<dim3(G3F/BN, Bb/BM), 256, SMEM_TOTAL>>>(
            px1h, Ff, pWxh + (size_t)G3F*Ff, Ff, gbx + G3F, pgx1, G3F, Ff, nullptr);
        k_gru<<<gruBlocks, 256>>>(pgx1, pgh + (size_t)Bb*G3F, pY + Bb*Ff, pYh + Bb*Ff,
                                  pouth + (size_t)t*Bb*Ff);
    }

    // regressor
    k_mgemm<EPI_LRELU><<<dim3(128/BN, (Ss*Bb)/BM), 256, SMEM_TOTAL>>>(
        pouth, Ff, prW1, Ff, rb1, phid, 128, Ff, nullptr);
    k_pose<<<(Ss*Bb*6 + 127)/128, 128>>>(rW2, rb2, (float*)d_out);

    if (out_size >= Ss*Bb*6 + MB*Ff)
        k_copyY<<<768, 256>>>((float*)d_out + Ss*Bb*6);
}

// round 9
// speedup vs baseline: 1.6933x; 1.0164x over previous
#include <cuda_runtime.h>
#include <cuda_fp16.h>
#include <math.h>
#include <stdint.h>

// ---------------- problem constants ----------------
#define Bb   256
#define Ss   32
#define VFd  512
#define IFd  256
#define Ff   768
#define Hh   1024
#define Ll   2
#define Kk   8
#define MB   (Ll*Bb)
#define G3F  (3*Ff)

// ---------------- GEMM tiling: 64x64 CTA, BK=128, 3-stage ----------------
#define BM 64
#define BN 64
#define BK 128
#define ROWB   272             // 128 halves (256B) + 16B pad -> conflict-free ldmatrix
#define PLANE  (64*ROWB)       // 17408
#define STAGE_BYTES (2*PLANE)  // 34816
#define NSTAGE 3
#define SMEM_TOTAL (NSTAGE*STAGE_BYTES)  // 104448

// ---------------- persistent device scratch ----------------
__device__ __align__(16) float  g_dt  [Ss*Bb];
__device__ __align__(16) float  g_Y   [MB*Ff];
__device__ __align__(16) __half g_Yh  [MB*Ff];
__device__ __align__(16) __half g_xh  [Ss*Bb*Ff];
__device__ __align__(16) float  g_a1  [MB*Hh];
__device__ __align__(16) __half g_h1h [MB*Hh];
__device__ __align__(16) __half g_h2h [MB*Hh];
__device__ __align__(16) float  g_Sf  [MB*Hh];
__device__ __align__(16) __half g_Sh  [MB*Hh];
__device__ __align__(16) __half g_x1h [Bb*Ff];
__device__ __align__(16) __half g_outh[Ss*Bb*Ff];
__device__ __align__(16) float  g_gx0 [Ss*Bb*G3F];
__device__ __align__(16) float  g_gh  [2*Bb*G3F];
__device__ __align__(16) float  g_gx1 [Bb*G3F];
__device__ __align__(16) float  g_hid [Ss*Bb*128];
__device__ __align__(16) float  g_c0  [Hh];
// fp16 weights
__device__ __align__(16) __half g_W0h [Hh*Ff];
__device__ __align__(16) __half g_W1h [Hh*Hh];
__device__ __align__(16) __half g_W2h [Ff*Hh];
__device__ __align__(16) __half g_W2Th[Hh*Ff];
__device__ __align__(16) float  g_W20f[Hh*Hh];
__device__ __align__(16) __half g_W20h[Hh*Hh];
__device__ __align__(16) __half g_Wxh [Ll*G3F*Ff];
__device__ __align__(16) __half g_Whh [Ll*G3F*Ff];
__device__ __align__(16) __half g_rW1h[128*Ff];

// ---------------- asm helpers ----------------
__device__ __forceinline__ uint32_t smem_u32(const void* p) {
    uint32_t a;
    asm("{ .reg .u64 t; cvta.to.shared.u64 t, %1; cvt.u32.u64 %0, t; }" : "=r"(a) : "l"(p));
    return a;
}
__device__ __forceinline__ void cp16(uint32_t dst, const void* src) {
    asm volatile("cp.async.cg.shared.global [%0], [%1], 16;" :: "r"(dst), "l"(src));
}
__device__ __forceinline__ void ldm_x4(uint32_t addr, uint32_t r[4]) {
    asm volatile("ldmatrix.sync.aligned.m8n8.x4.shared.b16 {%0,%1,%2,%3}, [%4];"
                 : "=r"(r[0]), "=r"(r[1]), "=r"(r[2]), "=r"(r[3]) : "r"(addr));
}
__device__ __forceinline__ void mma16816(float d[4], const uint32_t a[4],
                                         uint32_t b0, uint32_t b1) {
    asm volatile("mma.sync.aligned.m16n8k16.row.col.f32.f16.f16.f32 "
                 "{%0,%1,%2,%3}, {%4,%5,%6,%7}, {%8,%9}, {%0,%1,%2,%3};"
                 : "+f"(d[0]), "+f"(d[1]), "+f"(d[2]), "+f"(d[3])
                 : "r"(a[0]), "r"(a[1]), "r"(a[2]), "r"(a[3]), "r"(b0), "r"(b1));
}

// ---------------- core GEMM tile: 64x64, 256 threads ----------------
enum { EPI_STORE = 0, EPI_LRELU, EPI_A1, EPI_H2, EPI_DA1, EPI_YUPD };

template<int EPI, int KMODE>
__device__ __forceinline__ void gemm_core(
    const __half* __restrict__ A, int lda,
    const __half* __restrict__ Bm, int ldb,
    const float* __restrict__ bias,
    int m0, int n0, int Kd,
    float* __restrict__ Cf, int ldc,
    const float* __restrict__ dtv)
{
    extern __shared__ char smem[];
    __shared__ float sbias[BN];
    const uint32_t smem_base = smem_u32(smem);
    const int tid = threadIdx.x;
    const int wid = tid >> 5, lane = tid & 31;
    const int warp_m = wid & 1, warp_n = wid >> 1;

    if (tid < BN) {
        float b = bias ? bias[n0 + tid] : 0.0f;
        sbias[tid] = (EPI == EPI_YUPD) ? b * (float)Kk : b;
    }

    const int l_row = tid >> 2;          // 0..63
    const int l_c0  = tid & 3;           // 16B-chunk base, +4 per iter (16 chunks/row)

    auto issue_stage = [&](int c) {
        const int k0 = c * BK;
        const uint32_t sb = smem_base + (uint32_t)(c % NSTAGE) * STAGE_BYTES;
        const __half* Ar = A  + (size_t)(m0 + l_row) * lda + k0;
        const __half* Br = Bm + (size_t)(n0 + l_row) * ldb + k0;
        const uint32_t dst = sb + (uint32_t)l_row * ROWB;
#pragma unroll
        for (int i = 0; i < 4; i++) {
            const int c16 = l_c0 + i * 4;
            cp16(dst + c16*16,         Ar + c16*8);
            cp16(dst + PLANE + c16*16, Br + c16*8);
        }
        asm volatile("cp.async.commit_group;");
    };

    float acc[2][2][4];
#pragma unroll
    for (int mi = 0; mi < 2; mi++)
#pragma unroll
        for (int nj = 0; nj < 2; nj++)
#pragma unroll
            for (int e = 0; e < 4; e++) acc[mi][nj][e] = 0.0f;

    const int nc = Kd / BK;
    issue_stage(0);
    issue_stage(1);

    const int arow = lane & 15, acol8 = (lane >> 4) * 8;
    const int brow = ((lane >> 4) & 1) * 8 + (lane & 7);
    const int bcol8 = ((lane >> 3) & 1) * 8;
    const uint32_t aoff = (uint32_t)(warp_m*32 + arow) * ROWB + acol8 * 2;
    const uint32_t boff = PLANE + (uint32_t)(warp_n*16 + brow) * ROWB + bcol8 * 2;

    for (int c = 0; c < nc; c++) {
        if (c + 1 < nc) { asm volatile("cp.async.wait_group 1;"); }
        else            { asm volatile("cp.async.wait_group 0;"); }
        __syncthreads();
        if (c + 2 < nc) issue_stage(c + 2);

        const uint32_t sb = smem_base + (uint32_t)(c % NSTAGE) * STAGE_BYTES;
        // software-pipelined fragments over kk = 0..7 (BK=128 -> 8 k16 steps)
        uint32_t ah[2][2][4], bf[2][4];
        ldm_x4(sb + aoff, ah[0][0]);
        ldm_x4(sb + aoff + 16*ROWB, ah[0][1]);
        ldm_x4(sb + boff, bf[0]);
#pragma unroll
        for (int kk = 0; kk < 8; kk++) {
            const int cur = kk & 1, nxt = cur ^ 1;
            if (kk < 7) {
                ldm_x4(sb + aoff + (kk+1)*32, ah[nxt][0]);
                ldm_x4(sb + aoff + 16*ROWB + (kk+1)*32, ah[nxt][1]);
                ldm_x4(sb + boff + (kk+1)*32, bf[nxt]);
            }
#pragma unroll
            for (int mi = 0; mi < 2; mi++)
#pragma unroll
                for (int nj = 0; nj < 2; nj++)
                    mma16816(acc[mi][nj], ah[cur][mi], bf[cur][nj*2], bf[cur][nj*2+1]);
        }
        // no trailing __syncthreads: next iteration's wait+sync orders stage reuse
    }

    const int rbase = lane >> 2;
    const int cb2 = (lane & 3) * 2;
#pragma unroll
    for (int mi = 0; mi < 2; mi++) {
#pragma unroll
        for (int nj = 0; nj < 2; nj++) {
#pragma unroll
            for (int half = 0; half < 2; half++) {
                const int m  = m0 + warp_m*32 + mi*16 + rbase + half*8;
                const int nl = warp_n*16 + nj*8 + cb2;
                float v0 = acc[mi][nj][half*2 + 0] + sbias[nl];
                float v1 = acc[mi][nj][half*2 + 1] + sbias[nl + 1];
                const size_t o = (size_t)m * ldc + n0 + nl;
                if (EPI == EPI_A1) {
                    g_a1[o] = v0; g_a1[o+1] = v1;
                    *(__half2*)(g_h1h + o) = __floats2half2_rn(tanhf(v0), tanhf(v1));
                } else if (EPI == EPI_H2) {
                    v0 = tanhf(v0); v1 = tanhf(v1);
                    *(__half2*)(g_h2h + o) = __floats2half2_rn(v0, v1);
                    float s0, s1;
                    if (KMODE == 0) { s0 = v0; s1 = v1; }
                    else { s0 = g_Sf[o] + v0; s1 = g_Sf[o+1] + v1; }
                    g_Sf[o] = s0; g_Sf[o+1] = s1;
                    if (KMODE == 2)
                        *(__half2*)(g_Sh + o) = __floats2half2_rn(s0, s1);
                } else if (EPI == EPI_DA1) {
                    const float sub = __ldg(dtv + (m & (Bb - 1))) * (1.0f / Kk);
                    float a0 = g_a1[o]   + sub * v0;
                    float a1v = g_a1[o+1] + sub * v1;
                    g_a1[o] = a0; g_a1[o+1] = a1v;
                    *(__half2*)(g_h1h + o) = __floats2half2_rn(tanhf(a0), tanhf(a1v));
                } else if (EPI == EPI_YUPD) {
                    const float sub = __ldg(dtv + (m & (Bb - 1))) * (1.0f / Kk);
                    float y0 = g_Y[o]   + sub * v0;
                    float y1 = g_Y[o+1] + sub * v1;
                    g_Y[o] = y0; g_Y[o+1] = y1;
                    *(__half2*)(g_Yh + o) = __floats2half2_rn(y0, y1);
                } else if (EPI == EPI_LRELU) {
                    v0 = (v0 > 0.f) ? v0 : 0.1f*v0;
                    v1 = (v1 > 0.f) ? v1 : 0.1f*v1;
                    *(float2*)(Cf + o) = make_float2(v0, v1);
                } else {
                    *(float2*)(Cf + o) = make_float2(v0, v1);
                }
            }
        }
    }
}

// ---------------- kernels on top of the core ----------------
template<int EPI, int KMODE = 0>
__global__ void __launch_bounds__(256)
k_mgemm(const __half* __restrict__ A, int lda,
        const __half* __restrict__ Bm, int ldb,
        const float* __restrict__ bias,
        float* __restrict__ Cf, int ldc, int Kd,
        const float* __restrict__ dtv)
{
    gemm_core<EPI, KMODE>(A, lda, Bm, ldb, bias, blockIdx.y*64, blockIdx.x*64,
                          Kd, Cf, ldc, dtv);
}

// GRU layer-0 hidden projection
__global__ void __launch_bounds__(256)
k_gh0(const float* __restrict__ gbh)
{
    gemm_core<EPI_STORE, 0>(g_Yh, Ff, g_Whh, Ff, gbh,
                            blockIdx.y*64, blockIdx.x*64, Ff,
                            g_gh, G3F, nullptr);
}

// merged: z=0 -> gx1 = x1 @ Wx1^T + bx1 ; z=1 -> gh1 = Yh[L1] @ Wh1^T + bh1
__global__ void __launch_bounds__(256)
k_gxgh1(const float* __restrict__ gbx, const float* __restrict__ gbh)
{
    if (blockIdx.z == 0)
        gemm_core<EPI_STORE, 0>(g_x1h, Ff, g_Wxh + (size_t)G3F*Ff, Ff, gbx + G3F,
                                blockIdx.y*64, blockIdx.x*64, Ff,
                                g_gx1, G3F, nullptr);
    else
        gemm_core<EPI_STORE, 0>(g_Yh + (size_t)Bb*Ff, Ff, g_Whh + (size_t)G3F*Ff, Ff,
                                gbh + G3F,
                                blockIdx.y*64, blockIdx.x*64, Ff,
                                g_gh + (size_t)Bb*G3F, G3F, nullptr);
}

// ---------------- prep / small kernels ----------------
__global__ void k_a1init(const float* __restrict__ b0) {
    int stride = gridDim.x * blockDim.x;
    for (int i = blockIdx.x*blockDim.x + threadIdx.x; i < MB*Hh; i += stride) {
        float v = b0[i & (Hh - 1)];
        g_a1[i] = v;
        g_h1h[i] = __float2half_rn(tanhf(v));
    }
}

__global__ void k_cvt_all(const float* __restrict__ W0, const float* __restrict__ W1,
                          const float* __restrict__ W2o, const float* __restrict__ gWx,
                          const float* __restrict__ gWh, const float* __restrict__ rW1)
{
    const int n0 = Hh*Ff, n1 = n0 + Hh*Hh, n2 = n1 + Ff*Hh;
    const int n3 = n2 + Ll*G3F*Ff, n4 = n3 + Ll*G3F*Ff, n5 = n4 + 128*Ff;
    int stride = gridDim.x * blockDim.x;
    for (int i = blockIdx.x*blockDim.x + threadIdx.x; i < n5; i += stride) {
        float v; __half* d;
        if      (i < n0) { v = W0[i];        d = g_W0h  + i; }
        else if (i < n1) { v = W1[i - n0];   d = g_W1h  + (i - n0); }
        else if (i < n2) { v = W2o[i - n1];  d = g_W2h  + (i - n1); }
        else if (i < n3) { v = gWx[i - n2];  d = g_Wxh  + (i - n2); }
        else if (i < n4) { v = gWh[i - n3];  d = g_Whh  + (i - n3); }
        else             { v = rW1[i - n4];  d = g_rW1h + (i - n4); }
        *d = __float2half_rn(v);
    }
}

__global__ void k_cvt(const float* __restrict__ src, __half* __restrict__ dst, int n) {
    int stride = gridDim.x * blockDim.x;
    for (int i = blockIdx.x*blockDim.x + threadIdx.x; i < n; i += stride)
        dst[i] = __float2half_rn(src[i]);
}

__global__ void k_transpose(const float* __restrict__ src, __half* __restrict__ dst,
                            int R, int C) {
    int stride = gridDim.x * blockDim.x;
    for (int i = blockIdx.x*blockDim.x + threadIdx.x; i < R*C; i += stride) {
        int cc = i / R, rr = i % R;
        dst[(size_t)cc*R + rr] = __float2half_rn(src[(size_t)rr*C + cc]);
    }
}

__global__ void k_c0(const float* __restrict__ W0, const float* __restrict__ b2) {
    int i = blockIdx.x*blockDim.x + threadIdx.x;
    if (i >= Hh) return;
    const float* row = W0 + (size_t)i*Ff;
    float acc = 0.0f;
#pragma unroll 8
    for (int f = 0; f < Ff; f++) acc += row[f] * b2[f];
    g_c0[i] = acc;
}

__global__ void k_prep_x(const float* __restrict__ fv, const float* __restrict__ fi) {
    int stride = gridDim.x * blockDim.x;
    int total = Ss*Bb*Ff;
    for (int idx = blockIdx.x*blockDim.x + threadIdx.x; idx < total; idx += stride) {
        int f = idx % Ff;
        int sb = idx / Ff;
        int b = sb % Bb, s = sb / Bb;
        float v = (f < VFd) ? fv[(b*Ss + s)*VFd + f] : fi[(b*Ss + s)*IFd + (f - VFd)];
        g_xh[idx] = __float2half_rn(v);
    }
}

__global__ void k_prep_misc(const float* __restrict__ ts) {
    int stride = gridDim.x * blockDim.x;
    int gtid = blockIdx.x*blockDim.x + threadIdx.x;
    for (int i = gtid; i < MB*Ff; i += stride) {
        g_Y[i] = 0.0f; g_Yh[i] = __float2half(0.0f);
    }
    for (int i = gtid; i < Ss*Bb; i += stride) {
        int s = i / Bb, b = i % Bb;
        g_dt[i] = (s < Ss-1) ? (ts[b*Ss + s + 1] - ts[b*Ss + s]) : 0.0f;
    }
}

// ---------------- GRU elementwise combine ----------------
__global__ void k_gru(const float* __restrict__ gx, const float* __restrict__ gh,
                      float* __restrict__ h, __half* __restrict__ hh,
                      __half* __restrict__ xh)
{
    int idx = blockIdx.x*blockDim.x + threadIdx.x;
    if (idx >= Bb*Ff) return;
    int b = idx / Ff, f = idx % Ff;
    int o = b*G3F + f;
    float r  = 1.0f / (1.0f + expf(-(gx[o]        + gh[o]       )));
    float z  = 1.0f / (1.0f + expf(-(gx[o + Ff]   + gh[o + Ff]  )));
    float n  = tanhf(gx[o + 2*Ff] + r * gh[o + 2*Ff]);
    float hn = (1.0f - z) * n + z * h[idx];
    h[idx] = hn;
    __half hv = __float2half_rn(hn);
    hh[idx] = hv;
    xh[idx] = hv;
}

// ---------------- regressor second layer (N=6) ----------------
__global__ void k_pose(const float* __restrict__ W2, const float* __restrict__ b2,
                       float* __restrict__ outp)
{
    int idx = blockIdx.x*blockDim.x + threadIdx.x;
    if (idx >= Ss*Bb*6) return;
    int n = idx % 6;
    int m = idx / 6;
    int b = m % Bb, s = m / Bb;
    const float* hrow = g_hid + (size_t)m * 128;
    const float* wrow = W2 + n * 128;
    float acc = b2[n];
#pragma unroll 8
    for (int k = 0; k < 128; k++) acc += hrow[k] * wrow[k];
    outp[(b*Ss + s)*6 + n] = acc;
}

__global__ void k_copyY(float* __restrict__ outp) {
    int stride = gridDim.x * blockDim.x;
    for (int i = blockIdx.x*blockDim.x + threadIdx.x; i < MB*Ff; i += stride)
        outp[i] = g_Y[i];
}

// ---------------- launch ----------------
extern "C" void kernel_launch(void* const* d_in, const int* in_sizes, int n_in,
                              void* d_out, int out_size)
{
    const float* fv  = (const float*)d_in[0];
    const float* fi  = (const float*)d_in[1];
    const float* ts  = (const float*)d_in[2];
    const float* W0  = (const float*)d_in[3];
    const float* b0  = (const float*)d_in[4];
    const float* W1  = (const float*)d_in[5];
    const float* b1  = (const float*)d_in[6];
    const float* W2o = (const float*)d_in[7];
    const float* b2o = (const float*)d_in[8];
    const float* gWx = (const float*)d_in[9];
    const float* gWh = (const float*)d_in[10];
    const float* gbx = (const float*)d_in[11];
    const float* gbh = (const float*)d_in[12];
    const float* rW1 = (const float*)d_in[13];
    const float* rb1 = (const float*)d_in[14];
    const float* rW2 = (const float*)d_in[15];
    const float* rb2 = (const float*)d_in[16];

#define SETSMEM(K) cudaFuncSetAttribute(K, cudaFuncAttributeMaxDynamicSharedMemorySize, SMEM_TOTAL)
    SETSMEM((k_mgemm<EPI_STORE, 0>)); SETSMEM((k_mgemm<EPI_LRELU, 0>));
    SETSMEM((k_mgemm<EPI_A1, 0>));    SETSMEM((k_mgemm<EPI_DA1, 0>));
    SETSMEM((k_mgemm<EPI_YUPD, 0>));
    SETSMEM((k_mgemm<EPI_H2, 0>)); SETSMEM((k_mgemm<EPI_H2, 1>)); SETSMEM((k_mgemm<EPI_H2, 2>));
    SETSMEM(k_gh0); SETSMEM(k_gxgh1);
#undef SETSMEM

#define SYM(p, s) float* p; cudaGetSymbolAddress((void**)&p, s)
#define SYMH(p, s) __half* p; cudaGetSymbolAddress((void**)&p, s)
    SYM(pdt, g_dt); SYM(pgx0, g_gx0); SYM(pgx1, g_gx1); SYM(pgh, g_gh);
    SYM(phid, g_hid); SYM(pW20f, g_W20f); SYM(pc0, g_c0); SYM(pY, g_Y);
    SYMH(pxh, g_xh); SYMH(pouth, g_outh); SYMH(pYh, g_Yh);
    SYMH(ph1h, g_h1h); SYMH(ph2h, g_h2h); SYMH(pSh, g_Sh); SYMH(px1h, g_x1h);
    SYMH(pW0h, g_W0h); SYMH(pW1h, g_W1h); SYMH(pW2h, g_W2h);
    SYMH(pW2Th, g_W2Th); SYMH(pW20h, g_W20h);
    SYMH(pWxh, g_Wxh); SYMH(pWhh, g_Whh); SYMH(prW1, g_rW1h);
#undef SYM
#undef SYMH

    // ---- weight prep ----
    k_cvt_all<<<1024, 256>>>(W0, W1, W2o, gWx, gWh, rW1);
    k_transpose<<<512, 256>>>(W2o, pW2Th, Ff, Hh);
    k_c0<<<(Hh + 255)/256, 256>>>(W0, b2o);
    k_mgemm<EPI_STORE><<<dim3(Hh/BN, Hh/BM), 256, SMEM_TOTAL>>>(
        pW0h, Ff, pW2Th, Ff, nullptr, pW20f, Hh, Ff, nullptr);
    k_cvt<<<512, 256>>>(pW20f, pW20h, Hh*Hh);

    k_prep_x<<<512, 256>>>(fv, fi);
    k_prep_misc<<<512, 256>>>(ts);

    // hoisted layer-0 GRU input projection
    k_mgemm<EPI_STORE><<<dim3(G3F/BN, (Ss*Bb)/BM), 256, SMEM_TOTAL>>>(
        pxh, Ff, pWxh, Ff, gbx, pgx0, G3F, Ff, nullptr);

    const int gruBlocks = (Bb*Ff + 255) / 256;
    const dim3 gridH(Hh/BN, MB/BM);     // 16 x 8 = 128
    const dim3 gridYU(Ff/BN, MB/BM);    // 12 x 8 = 96
    const dim3 gridG(G3F/BN, Bb/BM);    // 36 x 4 = 144

    for (int t = 0; t < Ss; t++) {
        const float* dtv = pdt + t*Bb;
        if (t < Ss - 1) {   // t = Ss-1 has dt == 0 -> ODE is identity, skip
            if (t == 0)
                k_a1init<<<512, 256>>>(b0);
            else
                k_mgemm<EPI_A1><<<gridH, 256, SMEM_TOTAL>>>(
                    pYh, Ff, pW0h, Ff, b0, nullptr, Hh, Ff, nullptr);
            for (int k = 0; k < Kk; k++) {
                if (k == 0)
                    k_mgemm<EPI_H2, 0><<<gridH, 256, SMEM_TOTAL>>>(
                        ph1h, Hh, pW1h, Hh, b1, nullptr, Hh, Hh, nullptr);
                else if (k < Kk - 1)
                    k_mgemm<EPI_H2, 1><<<gridH, 256, SMEM_TOTAL>>>(
                        ph1h, Hh, pW1h, Hh, b1, nullptr, Hh, Hh, nullptr);
                else
                    k_mgemm<EPI_H2, 2><<<gridH, 256, SMEM_TOTAL>>>(
                        ph1h, Hh, pW1h, Hh, b1, nullptr, Hh, Hh, nullptr);
                if (k < Kk - 1)
                    k_mgemm<EPI_DA1><<<gridH, 256, SMEM_TOTAL>>>(
                        ph2h, Hh, pW20h, Hh, pc0, nullptr, Hh, Hh, dtv);
            }
            k_mgemm<EPI_YUPD><<<gridYU, 256, SMEM_TOTAL>>>(
                pSh, Hh, pW2h, Hh, b2o, nullptr, Ff, Hh, dtv);
        }
        // GRU: gh0 -> combine0 -> [gx1 + gh1 merged] -> combine1
        k_gh0<<<gridG, 256, SMEM_TOTAL>>>(gbh);
        k_gru<<<gruBlocks, 256>>>(pgx0 + (size_t)t*Bb*G3F, pgh, pY, pYh, px1h);
        k_gxgh1<<<dim3(G3F/BN, Bb/BM, 2), 256, SMEM_TOTAL>>>(gbx, gbh);
        k_gru<<<gruBlocks, 256>>>(pgx1, pgh + (size_t)Bb*G3F, pY + Bb*Ff, pYh + Bb*Ff,
                                  pouth + (size_t)t*Bb*Ff);
    }

    // regressor
    k_mgemm<EPI_LRELU><<<dim3(128/BN, (Ss*Bb)/BM), 256, SMEM_TOTAL>>>(
        pouth, Ff, prW1, Ff, rb1, phid, 128, Ff, nullptr);
    k_pose<<<(Ss*Bb*6 + 127)/128, 128>>>(rW2, rb2, (float*)d_out);

    if (out_size >= Ss*Bb*6 + MB*Ff)
        k_copyY<<<768, 256>>>((float*)d_out + Ss*Bb*6);
}

// round 10
// speedup vs baseline: 1.9674x; 1.1619x over previous
#include <cuda_runtime.h>
#include <cuda_fp16.h>
#include <math.h>
#include <stdint.h>

// ---------------- problem constants ----------------
#define Bb   256
#define Ss   32
#define VFd  512
#define IFd  256
#define Ff   768
#define Hh   1024
#define Ll   2
#define Kk   8
#define MB   (Ll*Bb)
#define G3F  (3*Ff)

// ---------------- GEMM tiling: 64x64 CTA, BK=128, 3-stage, 512 threads ----------------
#define BM 64
#define BN 64
#define BK 128
#define NTHR 512
#define ROWB   272             // 128 halves (256B) + 16B pad
#define PLANE  (64*ROWB)       // 17408
#define STAGE_BYTES (2*PLANE)  // 34816
#define NSTAGE 3
#define SMEM_TOTAL (NSTAGE*STAGE_BYTES)  // 104448

// ---------------- persistent device scratch ----------------
__device__ __align__(16) float  g_dt  [Ss*Bb];
__device__ __align__(16) float  g_Y   [MB*Ff];
__device__ __align__(16) __half g_Yh  [MB*Ff];
__device__ __align__(16) __half g_xh  [Ss*Bb*Ff];
__device__ __align__(16) float  g_a1  [MB*Hh];
__device__ __align__(16) __half g_h1h [MB*Hh];
__device__ __align__(16) __half g_h2h [MB*Hh];
__device__ __align__(16) float  g_Sf  [MB*Hh];
__device__ __align__(16) __half g_Sh  [MB*Hh];
__device__ __align__(16) __half g_x1h [Bb*Ff];
__device__ __align__(16) __half g_outh[Ss*Bb*Ff];
__device__ __align__(16) float  g_gx0 [Ss*Bb*G3F];
__device__ __align__(16) float  g_gh  [2*Bb*G3F];
__device__ __align__(16) float  g_gx1 [Bb*G3F];
__device__ __align__(16) float  g_hid [Ss*Bb*128];
__device__ __align__(16) float  g_c0  [Hh];
// fp16 weights
__device__ __align__(16) __half g_W0h [Hh*Ff];
__device__ __align__(16) __half g_W1h [Hh*Hh];
__device__ __align__(16) __half g_W2h [Ff*Hh];
__device__ __align__(16) __half g_W2Th[Hh*Ff];
__device__ __align__(16) float  g_W20f[Hh*Hh];
__device__ __align__(16) __half g_W20h[Hh*Hh];
__device__ __align__(16) __half g_Wxh [Ll*G3F*Ff];
__device__ __align__(16) __half g_Whh [Ll*G3F*Ff];
__device__ __align__(16) __half g_rW1h[128*Ff];

// ---------------- asm helpers ----------------
__device__ __forceinline__ uint32_t smem_u32(const void* p) {
    uint32_t a;
    asm("{ .reg .u64 t; cvta.to.shared.u64 t, %1; cvt.u32.u64 %0, t; }" : "=r"(a) : "l"(p));
    return a;
}
__device__ __forceinline__ void cp16(uint32_t dst, const void* src) {
    asm volatile("cp.async.cg.shared.global [%0], [%1], 16;" :: "r"(dst), "l"(src));
}
__device__ __forceinline__ void ldm_x4(uint32_t addr, uint32_t r[4]) {
    asm volatile("ldmatrix.sync.aligned.m8n8.x4.shared.b16 {%0,%1,%2,%3}, [%4];"
                 : "=r"(r[0]), "=r"(r[1]), "=r"(r[2]), "=r"(r[3]) : "r"(addr));
}
__device__ __forceinline__ void mma16816(float d[4], const uint32_t a[4],
                                         uint32_t b0, uint32_t b1) {
    asm volatile("mma.sync.aligned.m16n8k16.row.col.f32.f16.f16.f32 "
                 "{%0,%1,%2,%3}, {%4,%5,%6,%7}, {%8,%9}, {%0,%1,%2,%3};"
                 : "+f"(d[0]), "+f"(d[1]), "+f"(d[2]), "+f"(d[3])
                 : "r"(a[0]), "r"(a[1]), "r"(a[2]), "r"(a[3]), "r"(b0), "r"(b1));
}

// ---------------- core GEMM tile: 64x64, 512 threads (4x4 warps, 16x16 warp tile) ----------------
enum { EPI_STORE = 0, EPI_LRELU, EPI_A1, EPI_H2, EPI_DA1, EPI_YUPD };

template<int EPI, int KMODE>
__device__ __forceinline__ void gemm_core(
    const __half* __restrict__ A, int lda,
    const __half* __restrict__ Bm, int ldb,
    const float* __restrict__ bias,
    int m0, int n0, int Kd,
    float* __restrict__ Cf, int ldc,
    const float* __restrict__ dtv)
{
    extern __shared__ char smem[];
    __shared__ float sbias[BN];
    const uint32_t smem_base = smem_u32(smem);
    const int tid = threadIdx.x;
    const int wid = tid >> 5, lane = tid & 31;
    const int warp_m = wid & 3;      // 0..3 -> 16 rows each
    const int warp_n = wid >> 2;     // 0..3 -> 16 cols each

    if (tid < BN) {
        float b = bias ? bias[n0 + tid] : 0.0f;
        sbias[tid] = (EPI == EPI_YUPD) ? b * (float)Kk : b;
    }

    // loads: 2048 16B-chunks per stage (A:1024, B:1024), 512 threads -> 4 each
    const int l_row = tid >> 4;        // 0..31 (with +32 on second iter)
    const int l_c16 = tid & 15;        // 0..15

    auto issue_stage = [&](int c) {
        const int k0 = c * BK;
        const uint32_t sb = smem_base + (uint32_t)(c % NSTAGE) * STAGE_BYTES;
#pragma unroll
        for (int i = 0; i < 2; i++) {
            const int row = l_row + i * 32;
            const uint32_t dst = sb + (uint32_t)row * ROWB + l_c16 * 16;
            cp16(dst,         A  + (size_t)(m0 + row) * lda + k0 + l_c16 * 8);
            cp16(dst + PLANE, Bm + (size_t)(n0 + row) * ldb + k0 + l_c16 * 8);
        }
        asm volatile("cp.async.commit_group;");
    };

    float acc[2][4];
#pragma unroll
    for (int nj = 0; nj < 2; nj++)
#pragma unroll
        for (int e = 0; e < 4; e++) acc[nj][e] = 0.0f;

    const int nc = Kd / BK;
    issue_stage(0);
    issue_stage(1);

    const int arow = lane & 15, acol8 = (lane >> 4) * 8;
    const int brow = ((lane >> 4) & 1) * 8 + (lane & 7);
    const int bcol8 = ((lane >> 3) & 1) * 8;
    const uint32_t aoff = (uint32_t)(warp_m*16 + arow) * ROWB + acol8 * 2;
    const uint32_t boff = PLANE + (uint32_t)(warp_n*16 + brow) * ROWB + bcol8 * 2;

    for (int c = 0; c < nc; c++) {
        if (c + 1 < nc) { asm volatile("cp.async.wait_group 1;"); }
        else            { asm volatile("cp.async.wait_group 0;"); }
        __syncthreads();
        if (c + 2 < nc) issue_stage(c + 2);

        const uint32_t sb = smem_base + (uint32_t)(c % NSTAGE) * STAGE_BYTES;
        // software-pipelined fragments over kk = 0..7 (BK=128 -> 8 k16 steps)
        uint32_t ah[2][4], bf[2][4];
        ldm_x4(sb + aoff, ah[0]);
        ldm_x4(sb + boff, bf[0]);
#pragma unroll
        for (int kk = 0; kk < 8; kk++) {
            const int cur = kk & 1, nxt = cur ^ 1;
            if (kk < 7) {
                ldm_x4(sb + aoff + (kk+1)*32, ah[nxt]);
                ldm_x4(sb + boff + (kk+1)*32, bf[nxt]);
            }
            mma16816(acc[0], ah[cur], bf[cur][0], bf[cur][1]);
            mma16816(acc[1], ah[cur], bf[cur][2], bf[cur][3]);
        }
        // no trailing __syncthreads: next iteration's wait+sync orders stage reuse
    }

    const int rbase = lane >> 2;
    const int cb2 = (lane & 3) * 2;
#pragma unroll
    for (int nj = 0; nj < 2; nj++) {
#pragma unroll
        for (int half = 0; half < 2; half++) {
            const int m  = m0 + warp_m*16 + rbase + half*8;
            const int nl = warp_n*16 + nj*8 + cb2;
            float v0 = acc[nj][half*2 + 0] + sbias[nl];
            float v1 = acc[nj][half*2 + 1] + sbias[nl + 1];
            const size_t o = (size_t)m * ldc + n0 + nl;
            if (EPI == EPI_A1) {
                g_a1[o] = v0; g_a1[o+1] = v1;
                *(__half2*)(g_h1h + o) = __floats2half2_rn(tanhf(v0), tanhf(v1));
            } else if (EPI == EPI_H2) {
                v0 = tanhf(v0); v1 = tanhf(v1);
                *(__half2*)(g_h2h + o) = __floats2half2_rn(v0, v1);
                float s0, s1;
                if (KMODE == 0) { s0 = v0; s1 = v1; }
                else { s0 = g_Sf[o] + v0; s1 = g_Sf[o+1] + v1; }
                g_Sf[o] = s0; g_Sf[o+1] = s1;
                if (KMODE == 2)
                    *(__half2*)(g_Sh + o) = __floats2half2_rn(s0, s1);
            } else if (EPI == EPI_DA1) {
                const float sub = __ldg(dtv + (m & (Bb - 1))) * (1.0f / Kk);
                float a0 = g_a1[o]   + sub * v0;
                float a1v = g_a1[o+1] + sub * v1;
                g_a1[o] = a0; g_a1[o+1] = a1v;
                *(__half2*)(g_h1h + o) = __floats2half2_rn(tanhf(a0), tanhf(a1v));
            } else if (EPI == EPI_YUPD) {
                const float sub = __ldg(dtv + (m & (Bb - 1))) * (1.0f / Kk);
                float y0 = g_Y[o]   + sub * v0;
                float y1 = g_Y[o+1] + sub * v1;
                g_Y[o] = y0; g_Y[o+1] = y1;
                *(__half2*)(g_Yh + o) = __floats2half2_rn(y0, y1);
            } else if (EPI == EPI_LRELU) {
                v0 = (v0 > 0.f) ? v0 : 0.1f*v0;
                v1 = (v1 > 0.f) ? v1 : 0.1f*v1;
                *(float2*)(Cf + o) = make_float2(v0, v1);
            } else {
                *(float2*)(Cf + o) = make_float2(v0, v1);
            }
        }
    }
}

// ---------------- kernels on top of the core ----------------
template<int EPI, int KMODE = 0>
__global__ void __launch_bounds__(NTHR)
k_mgemm(const __half* __restrict__ A, int lda,
        const __half* __restrict__ Bm, int ldb,
        const float* __restrict__ bias,
        float* __restrict__ Cf, int ldc, int Kd,
        const float* __restrict__ dtv)
{
    gemm_core<EPI, KMODE>(A, lda, Bm, ldb, bias, blockIdx.y*64, blockIdx.x*64,
                          Kd, Cf, ldc, dtv);
}

// GRU layer-0 hidden projection
__global__ void __launch_bounds__(NTHR)
k_gh0(const float* __restrict__ gbh)
{
    gemm_core<EPI_STORE, 0>(g_Yh, Ff, g_Whh, Ff, gbh,
                            blockIdx.y*64, blockIdx.x*64, Ff,
                            g_gh, G3F, nullptr);
}

// merged: z=0 -> gx1 = x1 @ Wx1^T + bx1 ; z=1 -> gh1 = Yh[L1] @ Wh1^T + bh1
__global__ void __launch_bounds__(NTHR)
k_gxgh1(const float* __restrict__ gbx, const float* __restrict__ gbh)
{
    if (blockIdx.z == 0)
        gemm_core<EPI_STORE, 0>(g_x1h, Ff, g_Wxh + (size_t)G3F*Ff, Ff, gbx + G3F,
                                blockIdx.y*64, blockIdx.x*64, Ff,
                                g_gx1, G3F, nullptr);
    else
        gemm_core<EPI_STORE, 0>(g_Yh + (size_t)Bb*Ff, Ff, g_Whh + (size_t)G3F*Ff, Ff,
                                gbh + G3F,
                                blockIdx.y*64, blockIdx.x*64, Ff,
                                g_gh + (size_t)Bb*G3F, G3F, nullptr);
}

// ---------------- prep / small kernels ----------------
__global__ void k_a1init(const float* __restrict__ b0) {
    int stride = gridDim.x * blockDim.x;
    for (int i = blockIdx.x*blockDim.x + threadIdx.x; i < MB*Hh; i += stride) {
        float v = b0[i & (Hh - 1)];
        g_a1[i] = v;
        g_h1h[i] = __float2half_rn(tanhf(v));
    }
}

__global__ void k_cvt_all(const float* __restrict__ W0, const float* __restrict__ W1,
                          const float* __restrict__ W2o, const float* __restrict__ gWx,
                          const float* __restrict__ gWh, const float* __restrict__ rW1)
{
    const int n0 = Hh*Ff, n1 = n0 + Hh*Hh, n2 = n1 + Ff*Hh;
    const int n3 = n2 + Ll*G3F*Ff, n4 = n3 + Ll*G3F*Ff, n5 = n4 + 128*Ff;
    int stride = gridDim.x * blockDim.x;
    for (int i = blockIdx.x*blockDim.x + threadIdx.x; i < n5; i += stride) {
        float v; __half* d;
        if      (i < n0) { v = W0[i];        d = g_W0h  + i; }
        else if (i < n1) { v = W1[i - n0];   d = g_W1h  + (i - n0); }
        else if (i < n2) { v = W2o[i - n1];  d = g_W2h  + (i - n1); }
        else if (i < n3) { v = gWx[i - n2];  d = g_Wxh  + (i - n2); }
        else if (i < n4) { v = gWh[i - n3];  d = g_Whh  + (i - n3); }
        else             { v = rW1[i - n4];  d = g_rW1h + (i - n4); }
        *d = __float2half_rn(v);
    }
}

__global__ void k_cvt(const float* __restrict__ src, __half* __restrict__ dst, int n) {
    int stride = gridDim.x * blockDim.x;
    for (int i = blockIdx.x*blockDim.x + threadIdx.x; i < n; i += stride)
        dst[i] = __float2half_rn(src[i]);
}

__global__ void k_transpose(const float* __restrict__ src, __half* __restrict__ dst,
                            int R, int C) {
    int stride = gridDim.x * blockDim.x;
    for (int i = blockIdx.x*blockDim.x + threadIdx.x; i < R*C; i += stride) {
        int cc = i / R, rr = i % R;
        dst[(size_t)cc*R + rr] = __float2half_rn(src[(size_t)rr*C + cc]);
    }
}

__global__ void k_c0(const float* __restrict__ W0, const float* __restrict__ b2) {
    int i = blockIdx.x*blockDim.x + threadIdx.x;
    if (i >= Hh) return;
    const float* row = W0 + (size_t)i*Ff;
    float acc = 0.0f;
#pragma unroll 8
    for (int f = 0; f < Ff; f++) acc += row[f] * b2[f];
    g_c0[i] = acc;
}

__global__ void k_prep_x(const float* __restrict__ fv, const float* __restrict__ fi) {
    int stride = gridDim.x * blockDim.x;
    int total = Ss*Bb*Ff;
    for (int idx = blockIdx.x*blockDim.x + threadIdx.x; idx < total; idx += stride) {
        int f = idx % Ff;
        int sb = idx / Ff;
        int b = sb % Bb, s = sb / Bb;
        float v = (f < VFd) ? fv[(b*Ss + s)*VFd + f] : fi[(b*Ss + s)*IFd + (f - VFd)];
        g_xh[idx] = __float2half_rn(v);
    }
}

__global__ void k_prep_misc(const float* __restrict__ ts) {
    int stride = gridDim.x * blockDim.x;
    int gtid = blockIdx.x*blockDim.x + threadIdx.x;
    for (int i = gtid; i < MB*Ff; i += stride) {
        g_Y[i] = 0.0f; g_Yh[i] = __float2half(0.0f);
    }
    for (int i = gtid; i < Ss*Bb; i += stride) {
        int s = i / Bb, b = i % Bb;
        g_dt[i] = (s < Ss-1) ? (ts[b*Ss + s + 1] - ts[b*Ss + s]) : 0.0f;
    }
}

// ---------------- GRU elementwise combine ----------------
__global__ void k_gru(const float* __restrict__ gx, const float* __restrict__ gh,
                      float* __restrict__ h, __half* __restrict__ hh,
                      __half* __restrict__ xh)
{
    int idx = blockIdx.x*blockDim.x + threadIdx.x;
    if (idx >= Bb*Ff) return;
    int b = idx / Ff, f = idx % Ff;
    int o = b*G3F + f;
    float r  = 1.0f / (1.0f + expf(-(gx[o]        + gh[o]       )));
    float z  = 1.0f / (1.0f + expf(-(gx[o + Ff]   + gh[o + Ff]  )));
    float n  = tanhf(gx[o + 2*Ff] + r * gh[o + 2*Ff]);
    float hn = (1.0f - z) * n + z * h[idx];
    h[idx] = hn;
    __half hv = __float2half_rn(hn);
    hh[idx] = hv;
    xh[idx] = hv;
}

// ---------------- regressor second layer (N=6) ----------------
__global__ void k_pose(const float* __restrict__ W2, const float* __restrict__ b2,
                       float* __restrict__ outp)
{
    int idx = blockIdx.x*blockDim.x + threadIdx.x;
    if (idx >= Ss*Bb*6) return;
    int n = idx % 6;
    int m = idx / 6;
    int b = m % Bb, s = m / Bb;
    const float* hrow = g_hid + (size_t)m * 128;
    const float* wrow = W2 + n * 128;
    float acc = b2[n];
#pragma unroll 8
    for (int k = 0; k < 128; k++) acc += hrow[k] * wrow[k];
    outp[(b*Ss + s)*6 + n] = acc;
}

__global__ void k_copyY(float* __restrict__ outp) {
    int stride = gridDim.x * blockDim.x;
    for (int i = blockIdx.x*blockDim.x + threadIdx.x; i < MB*Ff; i += stride)
        outp[i] = g_Y[i];
}

// ---------------- launch ----------------
extern "C" void kernel_launch(void* const* d_in, const int* in_sizes, int n_in,
                              void* d_out, int out_size)
{
    const float* fv  = (const float*)d_in[0];
    const float* fi  = (const float*)d_in[1];
    const float* ts  = (const float*)d_in[2];
    const float* W0  = (const float*)d_in[3];
    const float* b0  = (const float*)d_in[4];
    const float* W1  = (const float*)d_in[5];
    const float* b1  = (const float*)d_in[6];
    const float* W2o = (const float*)d_in[7];
    const float* b2o = (const float*)d_in[8];
    const float* gWx = (const float*)d_in[9];
    const float* gWh = (const float*)d_in[10];
    const float* gbx = (const float*)d_in[11];
    const float* gbh = (const float*)d_in[12];
    const float* rW1 = (const float*)d_in[13];
    const float* rb1 = (const float*)d_in[14];
    const float* rW2 = (const float*)d_in[15];
    const float* rb2 = (const float*)d_in[16];

#define SETSMEM(K) cudaFuncSetAttribute(K, cudaFuncAttributeMaxDynamicSharedMemorySize, SMEM_TOTAL)
    SETSMEM((k_mgemm<EPI_STORE, 0>)); SETSMEM((k_mgemm<EPI_LRELU, 0>));
    SETSMEM((k_mgemm<EPI_A1, 0>));    SETSMEM((k_mgemm<EPI_DA1, 0>));
    SETSMEM((k_mgemm<EPI_YUPD, 0>));
    SETSMEM((k_mgemm<EPI_H2, 0>)); SETSMEM((k_mgemm<EPI_H2, 1>)); SETSMEM((k_mgemm<EPI_H2, 2>));
    SETSMEM(k_gh0); SETSMEM(k_gxgh1);
#undef SETSMEM

#define SYM(p, s) float* p; cudaGetSymbolAddress((void**)&p, s)
#define SYMH(p, s) __half* p; cudaGetSymbolAddress((void**)&p, s)
    SYM(pdt, g_dt); SYM(pgx0, g_gx0); SYM(pgx1, g_gx1); SYM(pgh, g_gh);
    SYM(phid, g_hid); SYM(pW20f, g_W20f); SYM(pc0, g_c0); SYM(pY, g_Y);
    SYMH(pxh, g_xh); SYMH(pouth, g_outh); SYMH(pYh, g_Yh);
    SYMH(ph1h, g_h1h); SYMH(ph2h, g_h2h); SYMH(pSh, g_Sh); SYMH(px1h, g_x1h);
    SYMH(pW0h, g_W0h); SYMH(pW1h, g_W1h); SYMH(pW2h, g_W2h);
    SYMH(pW2Th, g_W2Th); SYMH(pW20h, g_W20h);
    SYMH(pWxh, g_Wxh); SYMH(pWhh, g_Whh); SYMH(prW1, g_rW1h);
#undef SYM
#undef SYMH

    // ---- weight prep ----
    k_cvt_all<<<1024, 256>>>(W0, W1, W2o, gWx, gWh, rW1);
    k_transpose<<<512, 256>>>(W2o, pW2Th, Ff, Hh);
    k_c0<<<(Hh + 255)/256, 256>>>(W0, b2o);
    k_mgemm<EPI_STORE><<<dim3(Hh/BN, Hh/BM), NTHR, SMEM_TOTAL>>>(
        pW0h, Ff, pW2Th, Ff, nullptr, pW20f, Hh, Ff, nullptr);
    k_cvt<<<512, 256>>>(pW20f, pW20h, Hh*Hh);

    k_prep_x<<<512, 256>>>(fv, fi);
    k_prep_misc<<<512, 256>>>(ts);

    // hoisted layer-0 GRU input projection
    k_mgemm<EPI_STORE><<<dim3(G3F/BN, (Ss*Bb)/BM), NTHR, SMEM_TOTAL>>>(
        pxh, Ff, pWxh, Ff, gbx, pgx0, G3F, Ff, nullptr);

    const int gruBlocks = (Bb*Ff + 255) / 256;
    const dim3 gridH(Hh/BN, MB/BM);     // 16 x 8 = 128
    const dim3 gridYU(Ff/BN, MB/BM);    // 12 x 8 = 96
    const dim3 gridG(G3F/BN, Bb/BM);    // 36 x 4 = 144

    for (int t = 0; t < Ss; t++) {
        const float* dtv = pdt + t*Bb;
        if (t < Ss - 1) {   // t = Ss-1 has dt == 0 -> ODE is identity, skip
            if (t == 0)
                k_a1init<<<512, 256>>>(b0);
            else
                k_mgemm<EPI_A1><<<gridH, NTHR, SMEM_TOTAL>>>(
                    pYh, Ff, pW0h, Ff, b0, nullptr, Hh, Ff, nullptr);
            for (int k = 0; k < Kk; k++) {
                if (k == 0)
                    k_mgemm<EPI_H2, 0><<<gridH, NTHR, SMEM_TOTAL>>>(
                        ph1h, Hh, pW1h, Hh, b1, nullptr, Hh, Hh, nullptr);
                else if (k < Kk - 1)
                    k_mgemm<EPI_H2, 1><<<gridH, NTHR, SMEM_TOTAL>>>(
                        ph1h, Hh, pW1h, Hh, b1, nullptr, Hh, Hh, nullptr);
                else
                    k_mgemm<EPI_H2, 2><<<gridH, NTHR, SMEM_TOTAL>>>(
                        ph1h, Hh, pW1h, Hh, b1, nullptr, Hh, Hh, nullptr);
                if (k < Kk - 1)
                    k_mgemm<EPI_DA1><<<gridH, NTHR, SMEM_TOTAL>>>(
                        ph2h, Hh, pW20h, Hh, pc0, nullptr, Hh, Hh, dtv);
            }
            k_mgemm<EPI_YUPD><<<gridYU, NTHR, SMEM_TOTAL>>>(
                pSh, Hh, pW2h, Hh, b2o, nullptr, Ff, Hh, dtv);
        }
        // GRU: gh0 -> combine0 -> [gx1 + gh1 merged] -> combine1
        k_gh0<<<gridG, NTHR, SMEM_TOTAL>>>(gbh);
        k_gru<<<gruBlocks, 256>>>(pgx0 + (size_t)t*Bb*G3F, pgh, pY, pYh, px1h);
        k_gxgh1<<<dim3(G3F/BN, Bb/BM, 2), NTHR, SMEM_TOTAL>>>(gbx, gbh);
        k_gru<<<gruBlocks, 256>>>(pgx1, pgh + (size_t)Bb*G3F, pY + Bb*Ff, pYh + Bb*Ff,
                                  pouth + (size_t)t*Bb*Ff);
    }

    // regressor
    k_mgemm<EPI_LRELU><<<dim3(128/BN, (Ss*Bb)/BM), NTHR, SMEM_TOTAL>>>(
        pouth, Ff, prW1, Ff, rb1, phid, 128, Ff, nullptr);
    k_pose<<<(Ss*Bb*6 + 127)/128, 128>>>(rW2, rb2, (float*)d_out);

    if (out_size >= Ss*Bb*6 + MB*Ff)
        k_copyY<<<768, 256>>>((float*)d_out + Ss*Bb*6);
}